// round 10
// baseline (speedup 1.0000x reference)
#include <cuda_runtime.h>
#include <cuda_bf16.h>
#include <math.h>

#define Bdim 16
#define Tdim 24
#define Ndim 512
#define Ddim 64
#define Hdim 4
#define HD   16
#define Fdim 256
#define MTOK (Bdim*Tdim*Ndim)   // 196608
#define EPS  1e-5f

// XOR-quad swizzle for stride-64 fp32/tf32 smem tiles
#define IDX(r,c) (((r)<<6) | (((c)&3) | (((((c)>>2) ^ ((r)&7))&15) << 2)))

// ---------------- scratch (device-only references) ----------------
// q/k/v live in [B, N, T, D] layout; everything else token-major [B, T, N, D].
__device__ float d_q[MTOK*Ddim];
__device__ float d_k[MTOK*Ddim];
__device__ float d_v[MTOK*Ddim];
__device__ float d_att[MTOK*Ddim];
__device__ float d_h[MTOK*Ddim];
__device__ float d_p1[MTOK*Ddim];
__device__ float d_h2[MTOK*Ddim];
__device__ unsigned d_Ahat[Ndim*Ndim];   // tf32 bits, pre-converted
__device__ float d_dinv[Ndim];

__device__ __forceinline__ unsigned f2tf32(float x) {
    unsigned r;
    asm("cvt.rna.tf32.f32 %0, %1;" : "=r"(r) : "f"(x));
    return r;
}

__device__ __forceinline__ void mma_tf32(float c[4], unsigned a0, unsigned a1,
                                         unsigned a2, unsigned a3,
                                         unsigned b0, unsigned b1) {
    asm volatile(
        "mma.sync.aligned.m16n8k8.row.col.f32.tf32.tf32.f32 "
        "{%0,%1,%2,%3}, {%4,%5,%6,%7}, {%8,%9}, {%0,%1,%2,%3};"
        : "+f"(c[0]), "+f"(c[1]), "+f"(c[2]), "+f"(c[3])
        : "r"(a0), "r"(a1), "r"(a2), "r"(a3), "r"(b0), "r"(b1));
}

// 64x64x64 MMA tile: As [m][k], Bs [k][n], both tf32 swizzled. 8 warps.
__device__ __forceinline__ void mma_64x64(float acc[4][4], const unsigned* As,
                                          const unsigned* Bs, int mrow, int ncol, int lane) {
#pragma unroll
    for (int k8 = 0; k8 < 8; k8++) {
        int kk = k8 * 8;
        int ar = mrow + (lane >> 2), ac = kk + (lane & 3);
        unsigned a0 = As[IDX(ar,   ac)];
        unsigned a1 = As[IDX(ar+8, ac)];
        unsigned a2 = As[IDX(ar,   ac+4)];
        unsigned a3 = As[IDX(ar+8, ac+4)];
#pragma unroll
        for (int nb = 0; nb < 4; nb++) {
            int n0 = ncol + nb*8;
            unsigned b0 = Bs[IDX(kk + (lane & 3),     n0 + (lane >> 2))];
            unsigned b1 = Bs[IDX(kk + (lane & 3) + 4, n0 + (lane >> 2))];
            mma_tf32(acc[nb], a0, a1, a2, a3, b0, b1);
        }
    }
}

// shared LN helper: ys is swizzled fp32 [64][64]; scratch >= 640 floats
__device__ __forceinline__ void ln_epilogue(const float* ys, float* scratch,
                                            const float* g, const float* bb,
                                            float* out_base, int tx) {
    float* part_s = scratch;
    float* part_q = scratch + 256;
    float* mu     = scratch + 512;
    float* rs     = scratch + 576;
    {
        int row = tx >> 2, seg = tx & 3;
        float s = 0.f, q = 0.f;
#pragma unroll
        for (int cc = 0; cc < 16; cc++) {
            float v = ys[IDX(row, seg*16 + cc)];
            s += v; q += v*v;
        }
        part_s[tx] = s; part_q[tx] = q;
    }
    __syncthreads();
    if (tx < 64) {
        float S = part_s[tx*4] + part_s[tx*4+1] + part_s[tx*4+2] + part_s[tx*4+3];
        float Q = part_q[tx*4] + part_q[tx*4+1] + part_q[tx*4+2] + part_q[tx*4+3];
        float m = S * (1.0f/64.f);
        float var = Q * (1.0f/64.f) - m*m;
        mu[tx] = m; rs[tx] = rsqrtf(var + EPS);
    }
    __syncthreads();
#pragma unroll 4
    for (int i = tx; i < 4096; i += 256) {
        int r = i >> 6, c = i & 63;
        out_base[(size_t)r*64 + c] = (ys[IDX(r,c)] - mu[r]) * rs[r] * g[c] + bb[c];
    }
}

// ---------------- degree / Ahat ----------------
__global__ void deg_kernel(const float* __restrict__ adj) {
    int m = blockIdx.x, tx = threadIdx.x;
    float s = 0.f;
    for (int n = tx; n < Ndim; n += 256) s += adj[m*Ndim + n];
    __shared__ float red[256];
    red[tx] = s; __syncthreads();
#pragma unroll
    for (int st = 128; st > 0; st >>= 1) {
        if (tx < st) red[tx] += red[tx + st];
        __syncthreads();
    }
    if (tx == 0) d_dinv[m] = rsqrtf(fmaxf(red[0] + 1.0f, 1e-12f));
}

__global__ void ahat_kernel(const float* __restrict__ adj) {
    int m = blockIdx.x, n = threadIdx.x;
    float a = adj[m*Ndim + n] + (m == n ? 1.0f : 0.0f);
    d_Ahat[m*Ndim + n] = f2tf32(d_dinv[m] * a * d_dinv[n]);
}

// ---------------- fused QKV (tf32 mma), writes [B,N,T,D] ----------------
__global__ void qkv_gemm(const float* __restrict__ x,
                         const float* __restrict__ Wq, const float* __restrict__ bq,
                         const float* __restrict__ Wk, const float* __restrict__ bk,
                         const float* __restrict__ Wv, const float* __restrict__ bv) {
    __shared__ unsigned As[4096];
    __shared__ unsigned Wt[4096];
    int tx = threadIdx.x;
    int wid = tx >> 5, lane = tx & 31;
    int mrow = (wid >> 1) * 16, ncol = (wid & 1) * 32;
    size_t mbase = (size_t)blockIdx.x * 64;
    int b = (int)(mbase / (Tdim*Ndim));
    int rem = (int)(mbase % (Tdim*Ndim));
    int t = rem / Ndim, nbase = rem % Ndim;
#pragma unroll 4
    for (int i = tx; i < 4096; i += 256) {
        int r = i >> 6, c = i & 63;
        As[IDX(r,c)] = f2tf32(x[(mbase + r)*64 + c]);
    }
    const float* Wm[3] = {Wq, Wk, Wv};
    const float* bm[3] = {bq, bk, bv};
    float* Om[3] = {d_q, d_k, d_v};
#pragma unroll
    for (int m = 0; m < 3; m++) {
        __syncthreads();
        const float* W = Wm[m];
#pragma unroll 4
        for (int i = tx; i < 4096; i += 256) {
            int r = i >> 6, c = i & 63;
            Wt[IDX(r,c)] = f2tf32(W[r*64 + c]);
        }
        __syncthreads();
        float acc[4][4] = {};
        mma_64x64(acc, As, Wt, mrow, ncol, lane);
        float* O = Om[m];
        const float* bias = bm[m];
        int row = mrow + (lane >> 2);
#pragma unroll
        for (int nb = 0; nb < 4; nb++) {
            int col = ncol + nb*8 + 2*(lane & 3);
            float b0v = bias[col], b1v = bias[col+1];
            size_t o0 = ((size_t)(b*Ndim + nbase + row    )*Tdim + t)*64 + col;
            size_t o1 = ((size_t)(b*Ndim + nbase + row + 8)*Tdim + t)*64 + col;
            *(float2*)&O[o0] = make_float2(acc[nb][0] + b0v, acc[nb][1] + b1v);
            *(float2*)&O[o1] = make_float2(acc[nb][2] + b0v, acc[nb][3] + b1v);
        }
    }
}

// ---------------- temporal attention ----------------
__global__ void __launch_bounds__(256, 3) attn_kernel() {
    int bn = blockIdx.x;
    int b = bn / Ndim, n = bn % Ndim;
    size_t base = (size_t)bn * Tdim * Ddim;
    __shared__ __align__(16) float qs[Tdim][Ddim];
    __shared__ float kst[Ddim][25];
    __shared__ __align__(16) float vs[Tdim][Ddim];
    __shared__ float sc[Hdim][Tdim][Tdim];
    int tx = threadIdx.x;
    {
        const float4* q4 = (const float4*)(d_q + base);
        const float4* k4 = (const float4*)(d_k + base);
        const float4* v4 = (const float4*)(d_v + base);
        float4* qs4 = (float4*)&qs[0][0];
        float4* vs4 = (float4*)&vs[0][0];
        for (int i = tx; i < Tdim*16; i += 256) {
            qs4[i] = q4[i];
            vs4[i] = v4[i];
            float4 kv = k4[i];
            int t = i >> 4, d = (i & 15) * 4;
            kst[d+0][t] = kv.x; kst[d+1][t] = kv.y; kst[d+2][t] = kv.z; kst[d+3][t] = kv.w;
        }
    }
    __syncthreads();
    for (int i = tx; i < Hdim*Tdim*Tdim; i += 256) {
        int h = i / (Tdim*Tdim), r = i % (Tdim*Tdim);
        int tq = r / Tdim, tk = r % Tdim;
        float s = 0.f;
#pragma unroll
        for (int d = 0; d < HD; d++) s += qs[tq][h*HD + d] * kst[h*HD + d][tk];
        sc[h][tq][tk] = s * 0.25f;
    }
    __syncthreads();
    if (tx < Hdim*Tdim) {
        int h = tx / Tdim, tq = tx % Tdim;
        float m = -1e30f;
#pragma unroll
        for (int tk = 0; tk < Tdim; tk++) m = fmaxf(m, sc[h][tq][tk]);
        float sum = 0.f;
#pragma unroll
        for (int tk = 0; tk < Tdim; tk++) {
            float e = __expf(sc[h][tq][tk] - m);
            sc[h][tq][tk] = e; sum += e;
        }
        float inv = 1.0f / sum;
#pragma unroll
        for (int tk = 0; tk < Tdim; tk++) sc[h][tq][tk] *= inv;
    }
    __syncthreads();
    const float4* vs4 = (const float4*)&vs[0][0];
    float4* att4 = (float4*)d_att;
    for (int i = tx; i < Tdim*16; i += 256) {
        int tq = i >> 4, d4 = i & 15;
        int h = d4 >> 2;
        float4 o = make_float4(0.f, 0.f, 0.f, 0.f);
#pragma unroll
        for (int tk = 0; tk < Tdim; tk++) {
            float s = sc[h][tq][tk];
            float4 vv = vs4[tk*16 + d4];
            o.x += s*vv.x; o.y += s*vv.y; o.z += s*vv.z; o.w += s*vv.w;
        }
        att4[(((size_t)b*Tdim + tq)*Ndim + n)*16 + d4] = o;
    }
}

// ---------------- O-proj (tf32 mma) + residual + LN -> d_h ----------------
__global__ void oproj_ln(const float* __restrict__ x,
                         const float* __restrict__ Wo, const float* __restrict__ bo,
                         const float* __restrict__ g, const float* __restrict__ bb) {
    __shared__ unsigned As[4096];
    __shared__ unsigned Wt[4096];
    int tx = threadIdx.x;
    int wid = tx >> 5, lane = tx & 31;
    int mrow = (wid >> 1) * 16, ncol = (wid & 1) * 32;
    size_t mbase = (size_t)blockIdx.x * 64;
#pragma unroll 4
    for (int i = tx; i < 4096; i += 256) {
        int r = i >> 6, c = i & 63;
        As[IDX(r,c)] = f2tf32(d_att[(mbase + r)*64 + c]);
        Wt[IDX(r,c)] = f2tf32(Wo[r*64 + c]);
    }
    __syncthreads();
    float acc[4][4] = {};
    mma_64x64(acc, As, Wt, mrow, ncol, lane);
    __syncthreads();
    float* ys = (float*)As;
    {
        int row = mrow + (lane >> 2);
#pragma unroll
        for (int nb = 0; nb < 4; nb++) {
            int col = ncol + nb*8 + 2*(lane & 3);
            float2 x0 = *(const float2*)&x[(mbase + row    )*64 + col];
            float2 x1 = *(const float2*)&x[(mbase + row + 8)*64 + col];
            ys[IDX(row,   col  )] = acc[nb][0] + bo[col]   + x0.x;
            ys[IDX(row,   col+1)] = acc[nb][1] + bo[col+1] + x0.y;
            ys[IDX(row+8, col  )] = acc[nb][2] + bo[col]   + x1.x;
            ys[IDX(row+8, col+1)] = acc[nb][3] + bo[col+1] + x1.y;
        }
    }
    __syncthreads();
    ln_epilogue(ys, (float*)Wt, g, bb, d_h + mbase*64, tx);
}

// ---------------- graph stage 0: p1 = Ahat @ h ----------------
__global__ void graph_gemm0() {
    __shared__ unsigned As[4096];
    __shared__ unsigned Bs[4096];
    int tx = threadIdx.x;
    int wid = tx >> 5, lane = tx & 31;
    int mrow = (wid >> 1) * 16, ncol = (wid & 1) * 32;
    int mbase = blockIdx.x * 64;
    size_t hbase = (size_t)blockIdx.y * Ndim * Ddim;
    float acc[4][4] = {};
    for (int kt = 0; kt < 8; kt++) {
        __syncthreads();
#pragma unroll 4
        for (int i = tx; i < 4096; i += 256) {
            int r = i >> 6, c = i & 63;
            As[IDX(r,c)] = d_Ahat[(size_t)(mbase + r)*Ndim + kt*64 + c];
            Bs[IDX(r,c)] = f2tf32(d_h[hbase + (size_t)(kt*64 + r)*64 + c]);
        }
        __syncthreads();
        mma_64x64(acc, As, Bs, mrow, ncol, lane);
    }
    int row = mbase + mrow + (lane >> 2);
#pragma unroll
    for (int nb = 0; nb < 4; nb++) {
        int col = ncol + nb*8 + 2*(lane & 3);
        *(float2*)&d_p1[hbase + (size_t)row*64 + col]     = make_float2(acc[nb][0], acc[nb][1]);
        *(float2*)&d_p1[hbase + (size_t)(row+8)*64 + col] = make_float2(acc[nb][2], acc[nb][3]);
    }
}

// ---------------- graph stage 1 FUSED with gc-combine + residual + LN -> d_h2 ----------------
// p2_tile = sum_kt Ahat[mtile,kt] @ p1[kt]; then
// y = h + h@W0 + p1[mtile]@W1 + p2_tile@W2 + biases; LN -> d_h2
__global__ void graph_gemm1_fused(const float* __restrict__ gcW, const float* __restrict__ gcb,
                                  const float* __restrict__ g, const float* __restrict__ bb) {
    __shared__ unsigned As[4096];    // Ahat tile; later p2 (tf32), later ys (fp32)
    __shared__ unsigned Bs[4096];    // p1 k-tile; later gcW chunks; later LN scratch
    __shared__ unsigned P1m[4096];   // p1[mtile] captured
    __shared__ unsigned Hm[4096];    // h[mtile] tf32
    int tx = threadIdx.x;
    int wid = tx >> 5, lane = tx & 31;
    int mrow = (wid >> 1) * 16, ncol = (wid & 1) * 32;
    int mtile = blockIdx.x;
    int mbase = mtile * 64;
    size_t hbase = (size_t)blockIdx.y * Ndim * Ddim;
    float acc[4][4] = {};
    for (int kt = 0; kt < 8; kt++) {
        __syncthreads();
#pragma unroll 4
        for (int i = tx; i < 4096; i += 256) {
            int r = i >> 6, c = i & 63;
            As[IDX(r,c)] = d_Ahat[(size_t)(mbase + r)*Ndim + kt*64 + c];
            Bs[IDX(r,c)] = f2tf32(d_p1[hbase + (size_t)(kt*64 + r)*64 + c]);
        }
        __syncthreads();
        if (kt == mtile) {
#pragma unroll 4
            for (int i = tx; i < 4096; i += 256) P1m[i] = Bs[i];
        }
        mma_64x64(acc, As, Bs, mrow, ncol, lane);
    }
    __syncthreads();   // all reads of As/Bs done
    // store p2 tile (tf32) into As; load h tile; load gcW0 into Bs
    {
        int row = mrow + (lane >> 2);
#pragma unroll
        for (int nb = 0; nb < 4; nb++) {
            int col = ncol + nb*8 + 2*(lane & 3);
            As[IDX(row,   col  )] = f2tf32(acc[nb][0]);
            As[IDX(row,   col+1)] = f2tf32(acc[nb][1]);
            As[IDX(row+8, col  )] = f2tf32(acc[nb][2]);
            As[IDX(row+8, col+1)] = f2tf32(acc[nb][3]);
        }
    }
#pragma unroll 4
    for (int i = tx; i < 4096; i += 256) {
        int r = i >> 6, c = i & 63;
        Hm[IDX(r,c)] = f2tf32(d_h[hbase + (size_t)(mbase + r)*64 + c]);
        Bs[IDX(r,c)] = f2tf32(gcW[r*64 + c]);
    }
    __syncthreads();
#pragma unroll
    for (int i = 0; i < 4; i++)
#pragma unroll
        for (int j = 0; j < 4; j++) acc[i][j] = 0.f;
    mma_64x64(acc, Hm, Bs, mrow, ncol, lane);    // h @ W0
    __syncthreads();
#pragma unroll 4
    for (int i = tx; i < 4096; i += 256) {
        int r = i >> 6, c = i & 63;
        Bs[IDX(r,c)] = f2tf32(gcW[4096 + r*64 + c]);
    }
    __syncthreads();
    mma_64x64(acc, P1m, Bs, mrow, ncol, lane);   // p1 @ W1
    __syncthreads();
#pragma unroll 4
    for (int i = tx; i < 4096; i += 256) {
        int r = i >> 6, c = i & 63;
        Bs[IDX(r,c)] = f2tf32(gcW[2*4096 + r*64 + c]);
    }
    __syncthreads();
    mma_64x64(acc, As, Bs, mrow, ncol, lane);    // p2 @ W2
    __syncthreads();
    // ys = acc + gcb sums + residual h  (ys aliases Hm)
    float* ys = (float*)Hm;
    {
        int row = mrow + (lane >> 2);
#pragma unroll
        for (int nb = 0; nb < 4; nb++) {
            int col = ncol + nb*8 + 2*(lane & 3);
            float gb0 = gcb[col]   + gcb[64+col]   + gcb[128+col];
            float gb1 = gcb[col+1] + gcb[64+col+1] + gcb[128+col+1];
            float2 h0 = *(const float2*)&d_h[hbase + (size_t)(mbase + row    )*64 + col];
            float2 h1 = *(const float2*)&d_h[hbase + (size_t)(mbase + row + 8)*64 + col];
            ys[IDX(row,   col  )] = acc[nb][0] + gb0 + h0.x;
            ys[IDX(row,   col+1)] = acc[nb][1] + gb1 + h0.y;
            ys[IDX(row+8, col  )] = acc[nb][2] + gb0 + h1.x;
            ys[IDX(row+8, col+1)] = acc[nb][3] + gb1 + h1.y;
        }
    }
    __syncthreads();
    ln_epilogue(ys, (float*)Bs, g, bb, d_h2 + hbase + (size_t)mbase*64, tx);
}

// ---------------- FFN via tf32 mma + residual + LN ----------------
__global__ void ffn_ln(const float* __restrict__ W1, const float* __restrict__ b1,
                       const float* __restrict__ W2, const float* __restrict__ b2,
                       const float* __restrict__ g, const float* __restrict__ bb,
                       float* __restrict__ out) {
    __shared__ float    Asm[4096];
    __shared__ unsigned Wt[4096];
    __shared__ unsigned Gc[4096];
    int tx = threadIdx.x;
    int wid = tx >> 5, lane = tx & 31;
    int mrow = (wid >> 1) * 16, ncol = (wid & 1) * 32;
    size_t mbase = (size_t)blockIdx.x * 64;
#pragma unroll 4
    for (int i = tx; i < 4096; i += 256) {
        int r = i >> 6, c = i & 63;
        Asm[IDX(r,c)] = d_h2[(mbase + r)*64 + c];
    }
    float acc[4][4] = {};
#pragma unroll
    for (int ch = 0; ch < 4; ch++) {
        __syncthreads();
#pragma unroll 4
        for (int i = tx; i < 4096; i += 256) {
            int r = i >> 6, c = i & 63;
            Wt[IDX(r,c)] = f2tf32(W1[r*Fdim + ch*64 + c]);
        }
        __syncthreads();
        float p[4][4] = {};
#pragma unroll
        for (int k8 = 0; k8 < 8; k8++) {
            int kk = k8 * 8;
            int ar = mrow + (lane >> 2), ac = kk + (lane & 3);
            unsigned a0 = f2tf32(Asm[IDX(ar,   ac)]);
            unsigned a1 = f2tf32(Asm[IDX(ar+8, ac)]);
            unsigned a2 = f2tf32(Asm[IDX(ar,   ac+4)]);
            unsigned a3 = f2tf32(Asm[IDX(ar+8, ac+4)]);
#pragma unroll
            for (int nb = 0; nb < 4; nb++) {
                int n0 = ncol + nb*8;
                unsigned b0 = Wt[IDX(kk + (lane & 3),     n0 + (lane >> 2))];
                unsigned b1 = Wt[IDX(kk + (lane & 3) + 4, n0 + (lane >> 2))];
                mma_tf32(p[nb], a0, a1, a2, a3, b0, b1);
            }
        }
        {
            int row = mrow + (lane >> 2);
#pragma unroll
            for (int nb = 0; nb < 4; nb++) {
                int col = ncol + nb*8 + 2*(lane & 3);
                float bv0 = b1[ch*64 + col], bv1 = b1[ch*64 + col + 1];
                float v0 = p[nb][0] + bv0, v1 = p[nb][1] + bv1;
                float v2 = p[nb][2] + bv0, v3 = p[nb][3] + bv1;
                Gc[IDX(row,   col  )] = f2tf32(0.5f*v0*(1.0f + erff(v0*0.7071067811865476f)));
                Gc[IDX(row,   col+1)] = f2tf32(0.5f*v1*(1.0f + erff(v1*0.7071067811865476f)));
                Gc[IDX(row+8, col  )] = f2tf32(0.5f*v2*(1.0f + erff(v2*0.7071067811865476f)));
                Gc[IDX(row+8, col+1)] = f2tf32(0.5f*v3*(1.0f + erff(v3*0.7071067811865476f)));
            }
        }
        __syncthreads();
#pragma unroll 4
        for (int i = tx; i < 4096; i += 256) {
            int r = i >> 6, c = i & 63;
            Wt[IDX(r,c)] = f2tf32(W2[(ch*64 + r)*64 + c]);
        }
        __syncthreads();
        mma_64x64(acc, Gc, Wt, mrow, ncol, lane);
    }
    __syncthreads();
    float* ys = (float*)Wt;
    {
        int row = mrow + (lane >> 2);
#pragma unroll
        for (int nb = 0; nb < 4; nb++) {
            int col = ncol + nb*8 + 2*(lane & 3);
            ys[IDX(row,   col  )] = acc[nb][0] + b2[col]   + Asm[IDX(row,   col)];
            ys[IDX(row,   col+1)] = acc[nb][1] + b2[col+1] + Asm[IDX(row,   col+1)];
            ys[IDX(row+8, col  )] = acc[nb][2] + b2[col]   + Asm[IDX(row+8, col)];
            ys[IDX(row+8, col+1)] = acc[nb][3] + b2[col+1] + Asm[IDX(row+8, col+1)];
        }
    }
    __syncthreads();
    ln_epilogue(ys, (float*)Gc, g, bb, out + mbase*64, tx);
}

// ---------------- launch ----------------
extern "C" void kernel_launch(void* const* d_in, const int* in_sizes, int n_in,
                              void* d_out, int out_size) {
    const float* x   = (const float*)d_in[0];
    const float* adj = (const float*)d_in[1];
    const float* Wq  = (const float*)d_in[2];
    const float* bq  = (const float*)d_in[3];
    const float* Wk  = (const float*)d_in[4];
    const float* bk  = (const float*)d_in[5];
    const float* Wv  = (const float*)d_in[6];
    const float* bv  = (const float*)d_in[7];
    const float* Wo  = (const float*)d_in[8];
    const float* bo  = (const float*)d_in[9];
    const float* gcW = (const float*)d_in[10];
    const float* gcb = (const float*)d_in[11];
    const float* W1  = (const float*)d_in[12];
    const float* b1  = (const float*)d_in[13];
    const float* W2  = (const float*)d_in[14];
    const float* b2  = (const float*)d_in[15];
    const float* g_t = (const float*)d_in[16];
    const float* b_t = (const float*)d_in[17];
    const float* g_g = (const float*)d_in[18];
    const float* b_g = (const float*)d_in[19];
    const float* g_f = (const float*)d_in[20];
    const float* b_f = (const float*)d_in[21];
    float* out = (float*)d_out;

    deg_kernel<<<Ndim, 256>>>(adj);
    ahat_kernel<<<Ndim, Ndim>>>(adj);

    qkv_gemm<<<MTOK/64, 256>>>(x, Wq, bq, Wk, bk, Wv, bv);

    attn_kernel<<<Bdim*Ndim, 256>>>();

    oproj_ln<<<MTOK/64, 256>>>(x, Wo, bo, g_t, b_t);

    {
        dim3 grid(8, Bdim*Tdim);
        graph_gemm0<<<grid, 256>>>();
        graph_gemm1_fused<<<grid, 256>>>(gcW, gcb, g_g, b_g);
    }

    ffn_ln<<<MTOK/64, 256>>>(W1, b1, W2, b2, g_f, b_f, out);
}

// round 11
// speedup vs baseline: 1.3541x; 1.3541x over previous
#include <cuda_runtime.h>
#include <cuda_bf16.h>
#include <math.h>

#define Bdim 16
#define Tdim 24
#define Ndim 512
#define Ddim 64
#define Hdim 4
#define HD   16
#define Fdim 256
#define MTOK (Bdim*Tdim*Ndim)   // 196608
#define EPS  1e-5f

// XOR-quad swizzle for stride-64 fp32/tf32 smem tiles
#define IDX(r,c) (((r)<<6) | (((c)&3) | (((((c)>>2) ^ ((r)&7))&15) << 2)))

// ---------------- scratch (device-only references) ----------------
// q/k/v live in [B, N, T, D] layout; everything else token-major [B, T, N, D].
__device__ float d_q[MTOK*Ddim];
__device__ float d_k[MTOK*Ddim];
__device__ float d_v[MTOK*Ddim];
__device__ float d_att[MTOK*Ddim];
__device__ float d_h[MTOK*Ddim];
__device__ float d_p1[MTOK*Ddim];
__device__ float d_p2[MTOK*Ddim];
__device__ float d_h2[MTOK*Ddim];
__device__ unsigned d_Ahat[Ndim*Ndim];   // tf32 bits, pre-converted
__device__ float d_dinv[Ndim];

__device__ __forceinline__ unsigned f2tf32(float x) {
    unsigned r;
    asm("cvt.rna.tf32.f32 %0, %1;" : "=r"(r) : "f"(x));
    return r;
}

__device__ __forceinline__ void mma_tf32(float c[4], unsigned a0, unsigned a1,
                                         unsigned a2, unsigned a3,
                                         unsigned b0, unsigned b1) {
    asm volatile(
        "mma.sync.aligned.m16n8k8.row.col.f32.tf32.tf32.f32 "
        "{%0,%1,%2,%3}, {%4,%5,%6,%7}, {%8,%9}, {%0,%1,%2,%3};"
        : "+f"(c[0]), "+f"(c[1]), "+f"(c[2]), "+f"(c[3])
        : "r"(a0), "r"(a1), "r"(a2), "r"(a3), "r"(b0), "r"(b1));
}

// 64x64x64 MMA tile: As [m][k], Bs [k][n], both tf32 swizzled. 8 warps.
__device__ __forceinline__ void mma_64x64(float acc[4][4], const unsigned* As,
                                          const unsigned* Bs, int mrow, int ncol, int lane) {
#pragma unroll
    for (int k8 = 0; k8 < 8; k8++) {
        int kk = k8 * 8;
        int ar = mrow + (lane >> 2), ac = kk + (lane & 3);
        unsigned a0 = As[IDX(ar,   ac)];
        unsigned a1 = As[IDX(ar+8, ac)];
        unsigned a2 = As[IDX(ar,   ac+4)];
        unsigned a3 = As[IDX(ar+8, ac+4)];
#pragma unroll
        for (int nb = 0; nb < 4; nb++) {
            int n0 = ncol + nb*8;
            unsigned b0 = Bs[IDX(kk + (lane & 3),     n0 + (lane >> 2))];
            unsigned b1 = Bs[IDX(kk + (lane & 3) + 4, n0 + (lane >> 2))];
            mma_tf32(acc[nb], a0, a1, a2, a3, b0, b1);
        }
    }
}

// shared LN helper: ys is swizzled fp32 [64][64]; scratch >= 640 floats
__device__ __forceinline__ void ln_epilogue(const float* ys, float* scratch,
                                            const float* g, const float* bb,
                                            float* out_base, int tx) {
    float* part_s = scratch;
    float* part_q = scratch + 256;
    float* mu     = scratch + 512;
    float* rs     = scratch + 576;
    {
        int row = tx >> 2, seg = tx & 3;
        float s = 0.f, q = 0.f;
#pragma unroll
        for (int cc = 0; cc < 16; cc++) {
            float v = ys[IDX(row, seg*16 + cc)];
            s += v; q += v*v;
        }
        part_s[tx] = s; part_q[tx] = q;
    }
    __syncthreads();
    if (tx < 64) {
        float S = part_s[tx*4] + part_s[tx*4+1] + part_s[tx*4+2] + part_s[tx*4+3];
        float Q = part_q[tx*4] + part_q[tx*4+1] + part_q[tx*4+2] + part_q[tx*4+3];
        float m = S * (1.0f/64.f);
        float var = Q * (1.0f/64.f) - m*m;
        mu[tx] = m; rs[tx] = rsqrtf(var + EPS);
    }
    __syncthreads();
#pragma unroll 4
    for (int i = tx; i < 4096; i += 256) {
        int r = i >> 6, c = i & 63;
        out_base[(size_t)r*64 + c] = (ys[IDX(r,c)] - mu[r]) * rs[r] * g[c] + bb[c];
    }
}

// ---------------- degree / Ahat ----------------
__global__ void deg_kernel(const float* __restrict__ adj) {
    int m = blockIdx.x, tx = threadIdx.x;
    float s = 0.f;
    for (int n = tx; n < Ndim; n += 256) s += adj[m*Ndim + n];
    __shared__ float red[256];
    red[tx] = s; __syncthreads();
#pragma unroll
    for (int st = 128; st > 0; st >>= 1) {
        if (tx < st) red[tx] += red[tx + st];
        __syncthreads();
    }
    if (tx == 0) d_dinv[m] = rsqrtf(fmaxf(red[0] + 1.0f, 1e-12f));
}

__global__ void ahat_kernel(const float* __restrict__ adj) {
    int m = blockIdx.x, n = threadIdx.x;
    float a = adj[m*Ndim + n] + (m == n ? 1.0f : 0.0f);
    d_Ahat[m*Ndim + n] = f2tf32(d_dinv[m] * a * d_dinv[n]);
}

// ---------------- fused QKV (tf32 mma), writes [B,N,T,D] ----------------
__global__ void qkv_gemm(const float* __restrict__ x,
                         const float* __restrict__ Wq, const float* __restrict__ bq,
                         const float* __restrict__ Wk, const float* __restrict__ bk,
                         const float* __restrict__ Wv, const float* __restrict__ bv) {
    __shared__ unsigned As[4096];
    __shared__ unsigned Wt[4096];
    int tx = threadIdx.x;
    int wid = tx >> 5, lane = tx & 31;
    int mrow = (wid >> 1) * 16, ncol = (wid & 1) * 32;
    size_t mbase = (size_t)blockIdx.x * 64;
    int b = (int)(mbase / (Tdim*Ndim));
    int rem = (int)(mbase % (Tdim*Ndim));
    int t = rem / Ndim, nbase = rem % Ndim;
#pragma unroll 4
    for (int i = tx; i < 4096; i += 256) {
        int r = i >> 6, c = i & 63;
        As[IDX(r,c)] = f2tf32(x[(mbase + r)*64 + c]);
    }
    const float* Wm[3] = {Wq, Wk, Wv};
    const float* bm[3] = {bq, bk, bv};
    float* Om[3] = {d_q, d_k, d_v};
#pragma unroll
    for (int m = 0; m < 3; m++) {
        __syncthreads();
        const float* W = Wm[m];
#pragma unroll 4
        for (int i = tx; i < 4096; i += 256) {
            int r = i >> 6, c = i & 63;
            Wt[IDX(r,c)] = f2tf32(W[r*64 + c]);
        }
        __syncthreads();
        float acc[4][4] = {};
        mma_64x64(acc, As, Wt, mrow, ncol, lane);
        float* O = Om[m];
        const float* bias = bm[m];
        int row = mrow + (lane >> 2);
#pragma unroll
        for (int nb = 0; nb < 4; nb++) {
            int col = ncol + nb*8 + 2*(lane & 3);
            float b0v = bias[col], b1v = bias[col+1];
            size_t o0 = ((size_t)(b*Ndim + nbase + row    )*Tdim + t)*64 + col;
            size_t o1 = ((size_t)(b*Ndim + nbase + row + 8)*Tdim + t)*64 + col;
            *(float2*)&O[o0] = make_float2(acc[nb][0] + b0v, acc[nb][1] + b1v);
            *(float2*)&O[o1] = make_float2(acc[nb][2] + b0v, acc[nb][3] + b1v);
        }
    }
}

// ---------------- temporal attention (R9 version: no launch_bounds) ----------------
__global__ void attn_kernel() {
    int bn = blockIdx.x;
    int b = bn / Ndim, n = bn % Ndim;
    size_t base = (size_t)bn * Tdim * Ddim;
    __shared__ __align__(16) float qs[Tdim][Ddim];
    __shared__ float kst[Ddim][25];
    __shared__ __align__(16) float vs[Tdim][Ddim];
    __shared__ float sc[Hdim][Tdim][Tdim];
    int tx = threadIdx.x;
    {
        const float4* q4 = (const float4*)(d_q + base);
        const float4* k4 = (const float4*)(d_k + base);
        const float4* v4 = (const float4*)(d_v + base);
        float4* qs4 = (float4*)&qs[0][0];
        float4* vs4 = (float4*)&vs[0][0];
        for (int i = tx; i < Tdim*16; i += 256) {
            qs4[i] = q4[i];
            vs4[i] = v4[i];
            float4 kv = k4[i];
            int t = i >> 4, d = (i & 15) * 4;
            kst[d+0][t] = kv.x; kst[d+1][t] = kv.y; kst[d+2][t] = kv.z; kst[d+3][t] = kv.w;
        }
    }
    __syncthreads();
    for (int i = tx; i < Hdim*Tdim*Tdim; i += 256) {
        int h = i / (Tdim*Tdim), r = i % (Tdim*Tdim);
        int tq = r / Tdim, tk = r % Tdim;
        float s = 0.f;
#pragma unroll
        for (int d = 0; d < HD; d++) s += qs[tq][h*HD + d] * kst[h*HD + d][tk];
        sc[h][tq][tk] = s * 0.25f;
    }
    __syncthreads();
    if (tx < Hdim*Tdim) {
        int h = tx / Tdim, tq = tx % Tdim;
        float m = -1e30f;
#pragma unroll
        for (int tk = 0; tk < Tdim; tk++) m = fmaxf(m, sc[h][tq][tk]);
        float sum = 0.f;
#pragma unroll
        for (int tk = 0; tk < Tdim; tk++) {
            float e = __expf(sc[h][tq][tk] - m);
            sc[h][tq][tk] = e; sum += e;
        }
        float inv = 1.0f / sum;
#pragma unroll
        for (int tk = 0; tk < Tdim; tk++) sc[h][tq][tk] *= inv;
    }
    __syncthreads();
    const float4* vs4 = (const float4*)&vs[0][0];
    float4* att4 = (float4*)d_att;
    for (int i = tx; i < Tdim*16; i += 256) {
        int tq = i >> 4, d4 = i & 15;
        int h = d4 >> 2;
        float4 o = make_float4(0.f, 0.f, 0.f, 0.f);
#pragma unroll
        for (int tk = 0; tk < Tdim; tk++) {
            float s = sc[h][tq][tk];
            float4 vv = vs4[tk*16 + d4];
            o.x += s*vv.x; o.y += s*vv.y; o.z += s*vv.z; o.w += s*vv.w;
        }
        att4[(((size_t)b*Tdim + tq)*Ndim + n)*16 + d4] = o;
    }
}

// ---------------- O-proj (tf32 mma) + residual + LN -> d_h ----------------
__global__ void oproj_ln(const float* __restrict__ x,
                         const float* __restrict__ Wo, const float* __restrict__ bo,
                         const float* __restrict__ g, const float* __restrict__ bb) {
    __shared__ unsigned As[4096];
    __shared__ unsigned Wt[4096];
    int tx = threadIdx.x;
    int wid = tx >> 5, lane = tx & 31;
    int mrow = (wid >> 1) * 16, ncol = (wid & 1) * 32;
    size_t mbase = (size_t)blockIdx.x * 64;
#pragma unroll 4
    for (int i = tx; i < 4096; i += 256) {
        int r = i >> 6, c = i & 63;
        As[IDX(r,c)] = f2tf32(d_att[(mbase + r)*64 + c]);
        Wt[IDX(r,c)] = f2tf32(Wo[r*64 + c]);
    }
    __syncthreads();
    float acc[4][4] = {};
    mma_64x64(acc, As, Wt, mrow, ncol, lane);
    __syncthreads();
    float* ys = (float*)As;
    {
        int row = mrow + (lane >> 2);
#pragma unroll
        for (int nb = 0; nb < 4; nb++) {
            int col = ncol + nb*8 + 2*(lane & 3);
            float2 x0 = *(const float2*)&x[(mbase + row    )*64 + col];
            float2 x1 = *(const float2*)&x[(mbase + row + 8)*64 + col];
            ys[IDX(row,   col  )] = acc[nb][0] + bo[col]   + x0.x;
            ys[IDX(row,   col+1)] = acc[nb][1] + bo[col+1] + x0.y;
            ys[IDX(row+8, col  )] = acc[nb][2] + bo[col]   + x1.x;
            ys[IDX(row+8, col+1)] = acc[nb][3] + bo[col+1] + x1.y;
        }
    }
    __syncthreads();
    ln_epilogue(ys, (float*)Wt, g, bb, d_h + mbase*64, tx);
}

// ---------------- graph GEMM via tf32 mma (Ahat pre-converted) ----------------
__global__ void graph_gemm_tf32(int stage) {
    const float* __restrict__ Hin = stage ? (const float*)d_p1 : (const float*)d_h;
    float* __restrict__ Hout      = stage ? d_p2 : d_p1;
    __shared__ unsigned As[4096];
    __shared__ unsigned Bs[4096];
    int tx = threadIdx.x;
    int wid = tx >> 5, lane = tx & 31;
    int mrow = (wid >> 1) * 16, ncol = (wid & 1) * 32;
    int mbase = blockIdx.x * 64;
    size_t hbase = (size_t)blockIdx.y * Ndim * Ddim;
    float acc[4][4] = {};
    for (int kt = 0; kt < 8; kt++) {
        __syncthreads();
#pragma unroll 4
        for (int i = tx; i < 4096; i += 256) {
            int r = i >> 6, c = i & 63;
            As[IDX(r,c)] = d_Ahat[(size_t)(mbase + r)*Ndim + kt*64 + c];
            Bs[IDX(r,c)] = f2tf32(Hin[hbase + (size_t)(kt*64 + r)*64 + c]);
        }
        __syncthreads();
        mma_64x64(acc, As, Bs, mrow, ncol, lane);
    }
    int row = mbase + mrow + (lane >> 2);
#pragma unroll
    for (int nb = 0; nb < 4; nb++) {
        int col = ncol + nb*8 + 2*(lane & 3);
        *(float2*)&Hout[hbase + (size_t)row*64 + col]     = make_float2(acc[nb][0], acc[nb][1]);
        *(float2*)&Hout[hbase + (size_t)(row+8)*64 + col] = make_float2(acc[nb][2], acc[nb][3]);
    }
}

// ---------------- gc combine (3x tf32 mma) + residual + LN -> d_h2 ----------------
__global__ void gcomb_ln(const float* __restrict__ gcW, const float* __restrict__ gcb,
                         const float* __restrict__ g, const float* __restrict__ bb) {
    __shared__ unsigned In[4096];   // later ys
    __shared__ unsigned Ws[4096];   // later LN scratch
    int tx = threadIdx.x;
    int wid = tx >> 5, lane = tx & 31;
    int mrow = (wid >> 1) * 16, ncol = (wid & 1) * 32;
    size_t mbase = (size_t)blockIdx.x * 64;
    float acc[4][4] = {};
#pragma unroll
    for (int s = 0; s < 3; s++) {
        const float* Hin = (s == 0) ? (const float*)d_h : (s == 1) ? (const float*)d_p1 : (const float*)d_p2;
        __syncthreads();
#pragma unroll 4
        for (int i = tx; i < 4096; i += 256) {
            int r = i >> 6, c = i & 63;
            In[IDX(r,c)] = f2tf32(Hin[(mbase + r)*64 + c]);
            Ws[IDX(r,c)] = f2tf32(gcW[s*4096 + r*64 + c]);
        }
        __syncthreads();
        mma_64x64(acc, In, Ws, mrow, ncol, lane);
    }
    __syncthreads();
    float* ys = (float*)In;
    {
        int row = mrow + (lane >> 2);
#pragma unroll
        for (int nb = 0; nb < 4; nb++) {
            int col = ncol + nb*8 + 2*(lane & 3);
            float gb0 = gcb[col]   + gcb[64+col]   + gcb[128+col];
            float gb1 = gcb[col+1] + gcb[64+col+1] + gcb[128+col+1];
            float2 h0 = *(const float2*)&d_h[(mbase + row    )*64 + col];
            float2 h1 = *(const float2*)&d_h[(mbase + row + 8)*64 + col];
            ys[IDX(row,   col  )] = acc[nb][0] + gb0 + h0.x;
            ys[IDX(row,   col+1)] = acc[nb][1] + gb1 + h0.y;
            ys[IDX(row+8, col  )] = acc[nb][2] + gb0 + h1.x;
            ys[IDX(row+8, col+1)] = acc[nb][3] + gb1 + h1.y;
        }
    }
    __syncthreads();
    ln_epilogue(ys, (float*)Ws, g, bb, d_h2 + mbase*64, tx);
}

// ---------------- FFN via tf32 mma + residual + LN ----------------
__global__ void ffn_ln(const float* __restrict__ W1, const float* __restrict__ b1,
                       const float* __restrict__ W2, const float* __restrict__ b2,
                       const float* __restrict__ g, const float* __restrict__ bb,
                       float* __restrict__ out) {
    __shared__ float    Asm[4096];
    __shared__ unsigned Wt[4096];
    __shared__ unsigned Gc[4096];
    int tx = threadIdx.x;
    int wid = tx >> 5, lane = tx & 31;
    int mrow = (wid >> 1) * 16, ncol = (wid & 1) * 32;
    size_t mbase = (size_t)blockIdx.x * 64;
#pragma unroll 4
    for (int i = tx; i < 4096; i += 256) {
        int r = i >> 6, c = i & 63;
        Asm[IDX(r,c)] = d_h2[(mbase + r)*64 + c];
    }
    float acc[4][4] = {};
#pragma unroll
    for (int ch = 0; ch < 4; ch++) {
        __syncthreads();
#pragma unroll 4
        for (int i = tx; i < 4096; i += 256) {
            int r = i >> 6, c = i & 63;
            Wt[IDX(r,c)] = f2tf32(W1[r*Fdim + ch*64 + c]);
        }
        __syncthreads();
        float p[4][4] = {};
#pragma unroll
        for (int k8 = 0; k8 < 8; k8++) {
            int kk = k8 * 8;
            int ar = mrow + (lane >> 2), ac = kk + (lane & 3);
            unsigned a0 = f2tf32(Asm[IDX(ar,   ac)]);
            unsigned a1 = f2tf32(Asm[IDX(ar+8, ac)]);
            unsigned a2 = f2tf32(Asm[IDX(ar,   ac+4)]);
            unsigned a3 = f2tf32(Asm[IDX(ar+8, ac+4)]);
#pragma unroll
            for (int nb = 0; nb < 4; nb++) {
                int n0 = ncol + nb*8;
                unsigned b0 = Wt[IDX(kk + (lane & 3),     n0 + (lane >> 2))];
                unsigned b1 = Wt[IDX(kk + (lane & 3) + 4, n0 + (lane >> 2))];
                mma_tf32(p[nb], a0, a1, a2, a3, b0, b1);
            }
        }
        {
            int row = mrow + (lane >> 2);
#pragma unroll
            for (int nb = 0; nb < 4; nb++) {
                int col = ncol + nb*8 + 2*(lane & 3);
                float bv0 = b1[ch*64 + col], bv1 = b1[ch*64 + col + 1];
                float v0 = p[nb][0] + bv0, v1 = p[nb][1] + bv1;
                float v2 = p[nb][2] + bv0, v3 = p[nb][3] + bv1;
                Gc[IDX(row,   col  )] = f2tf32(0.5f*v0*(1.0f + erff(v0*0.7071067811865476f)));
                Gc[IDX(row,   col+1)] = f2tf32(0.5f*v1*(1.0f + erff(v1*0.7071067811865476f)));
                Gc[IDX(row+8, col  )] = f2tf32(0.5f*v2*(1.0f + erff(v2*0.7071067811865476f)));
                Gc[IDX(row+8, col+1)] = f2tf32(0.5f*v3*(1.0f + erff(v3*0.7071067811865476f)));
            }
        }
        __syncthreads();
#pragma unroll 4
        for (int i = tx; i < 4096; i += 256) {
            int r = i >> 6, c = i & 63;
            Wt[IDX(r,c)] = f2tf32(W2[(ch*64 + r)*64 + c]);
        }
        __syncthreads();
        mma_64x64(acc, Gc, Wt, mrow, ncol, lane);
    }
    __syncthreads();
    float* ys = (float*)Wt;
    {
        int row = mrow + (lane >> 2);
#pragma unroll
        for (int nb = 0; nb < 4; nb++) {
            int col = ncol + nb*8 + 2*(lane & 3);
            ys[IDX(row,   col  )] = acc[nb][0] + b2[col]   + Asm[IDX(row,   col)];
            ys[IDX(row,   col+1)] = acc[nb][1] + b2[col+1] + Asm[IDX(row,   col+1)];
            ys[IDX(row+8, col  )] = acc[nb][2] + b2[col]   + Asm[IDX(row+8, col)];
            ys[IDX(row+8, col+1)] = acc[nb][3] + b2[col+1] + Asm[IDX(row+8, col+1)];
        }
    }
    __syncthreads();
    ln_epilogue(ys, (float*)Gc, g, bb, out + mbase*64, tx);
}

// ---------------- launch ----------------
extern "C" void kernel_launch(void* const* d_in, const int* in_sizes, int n_in,
                              void* d_out, int out_size) {
    const float* x   = (const float*)d_in[0];
    const float* adj = (const float*)d_in[1];
    const float* Wq  = (const float*)d_in[2];
    const float* bq  = (const float*)d_in[3];
    const float* Wk  = (const float*)d_in[4];
    const float* bk  = (const float*)d_in[5];
    const float* Wv  = (const float*)d_in[6];
    const float* bv  = (const float*)d_in[7];
    const float* Wo  = (const float*)d_in[8];
    const float* bo  = (const float*)d_in[9];
    const float* gcW = (const float*)d_in[10];
    const float* gcb = (const float*)d_in[11];
    const float* W1  = (const float*)d_in[12];
    const float* b1  = (const float*)d_in[13];
    const float* W2  = (const float*)d_in[14];
    const float* b2  = (const float*)d_in[15];
    const float* g_t = (const float*)d_in[16];
    const float* b_t = (const float*)d_in[17];
    const float* g_g = (const float*)d_in[18];
    const float* b_g = (const float*)d_in[19];
    const float* g_f = (const float*)d_in[20];
    const float* b_f = (const float*)d_in[21];
    float* out = (float*)d_out;

    deg_kernel<<<Ndim, 256>>>(adj);
    ahat_kernel<<<Ndim, Ndim>>>(adj);

    qkv_gemm<<<MTOK/64, 256>>>(x, Wq, bq, Wk, bk, Wv, bv);

    attn_kernel<<<Bdim*Ndim, 256>>>();

    oproj_ln<<<MTOK/64, 256>>>(x, Wo, bo, g_t, b_t);

    {
        dim3 grid(8, Bdim*Tdim);
        graph_gemm_tf32<<<grid, 256>>>(0);
        graph_gemm_tf32<<<grid, 256>>>(1);
    }
    gcomb_ln<<<MTOK/64, 256>>>(gcW, gcb, g_g, b_g);

    ffn_ln<<<MTOK/64, 256>>>(W1, b1, W2, b2, g_f, b_f, out);
}

// round 15
// speedup vs baseline: 1.7474x; 1.2905x over previous
#include <cuda_runtime.h>
#include <cuda_bf16.h>
#include <math.h>
#include <stdint.h>

#define Bdim 16
#define Tdim 24
#define Ndim 512
#define Ddim 64
#define Hdim 4
#define HD   16
#define Fdim 256
#define MTOK (Bdim*Tdim*Ndim)   // 196608
#define EPS  1e-5f

// XOR-quad swizzle for stride-64 fp32/tf32 smem tiles
#define IDX(r,c) (((r)<<6) | (((c)&3) | (((((c)>>2) ^ ((r)&7))&15) << 2)))

// ---------------- scratch (device-only references) ----------------
__device__ float d_q[MTOK*Ddim];
__device__ float d_k[MTOK*Ddim];
__device__ float d_v[MTOK*Ddim];
__device__ float d_att[MTOK*Ddim];
__device__ float d_h[MTOK*Ddim];
__device__ float d_p1[MTOK*Ddim];
__device__ float d_p2[MTOK*Ddim];
__device__ float d_h2[MTOK*Ddim];
__device__ unsigned d_Ahat[Ndim*Ndim];   // tf32 bits, pre-converted
__device__ float d_dinv[Ndim];

__device__ __forceinline__ unsigned f2tf32(float x) {
    unsigned r;
    asm("cvt.rna.tf32.f32 %0, %1;" : "=r"(r) : "f"(x));
    return r;
}

__device__ __forceinline__ void cp16(unsigned int dst, const void* src) {
    asm volatile("cp.async.cg.shared.global [%0], [%1], 16;" :: "r"(dst), "l"(src));
}

__device__ __forceinline__ void mma_tf32(float c[4], unsigned a0, unsigned a1,
                                         unsigned a2, unsigned a3,
                                         unsigned b0, unsigned b1) {
    asm volatile(
        "mma.sync.aligned.m16n8k8.row.col.f32.tf32.tf32.f32 "
        "{%0,%1,%2,%3}, {%4,%5,%6,%7}, {%8,%9}, {%0,%1,%2,%3};"
        : "+f"(c[0]), "+f"(c[1]), "+f"(c[2]), "+f"(c[3])
        : "r"(a0), "r"(a1), "r"(a2), "r"(a3), "r"(b0), "r"(b1));
}

// 64x64x64 MMA tile: As [m][k], Bs [k][n], both tf32 swizzled. 8 warps.
__device__ __forceinline__ void mma_64x64(float acc[4][4], const unsigned* As,
                                          const unsigned* Bs, int mrow, int ncol, int lane) {
#pragma unroll
    for (int k8 = 0; k8 < 8; k8++) {
        int kk = k8 * 8;
        int ar = mrow + (lane >> 2), ac = kk + (lane & 3);
        unsigned a0 = As[IDX(ar,   ac)];
        unsigned a1 = As[IDX(ar+8, ac)];
        unsigned a2 = As[IDX(ar,   ac+4)];
        unsigned a3 = As[IDX(ar+8, ac+4)];
#pragma unroll
        for (int nb = 0; nb < 4; nb++) {
            int n0 = ncol + nb*8;
            unsigned b0 = Bs[IDX(kk + (lane & 3),     n0 + (lane >> 2))];
            unsigned b1 = Bs[IDX(kk + (lane & 3) + 4, n0 + (lane >> 2))];
            mma_tf32(acc[nb], a0, a1, a2, a3, b0, b1);
        }
    }
}

// Variant: Bs holds raw fp32 bits; convert at fragment load.
__device__ __forceinline__ void mma_64x64_bcvt(float acc[4][4], const unsigned* As,
                                               const unsigned* Bs, int mrow, int ncol, int lane) {
#pragma unroll
    for (int k8 = 0; k8 < 8; k8++) {
        int kk = k8 * 8;
        int ar = mrow + (lane >> 2), ac = kk + (lane & 3);
        unsigned a0 = As[IDX(ar,   ac)];
        unsigned a1 = As[IDX(ar+8, ac)];
        unsigned a2 = As[IDX(ar,   ac+4)];
        unsigned a3 = As[IDX(ar+8, ac+4)];
#pragma unroll
        for (int nb = 0; nb < 4; nb++) {
            int n0 = ncol + nb*8;
            unsigned b0 = f2tf32(__uint_as_float(Bs[IDX(kk + (lane & 3),     n0 + (lane >> 2))]));
            unsigned b1 = f2tf32(__uint_as_float(Bs[IDX(kk + (lane & 3) + 4, n0 + (lane >> 2))]));
            mma_tf32(acc[nb], a0, a1, a2, a3, b0, b1);
        }
    }
}

// shared LN helper: ys is swizzled fp32 [64][64]; scratch >= 640 floats
__device__ __forceinline__ void ln_epilogue(const float* ys, float* scratch,
                                            const float* g, const float* bb,
                                            float* out_base, int tx) {
    float* part_s = scratch;
    float* part_q = scratch + 256;
    float* mu     = scratch + 512;
    float* rs     = scratch + 576;
    {
        int row = tx >> 2, seg = tx & 3;
        float s = 0.f, q = 0.f;
#pragma unroll
        for (int cc = 0; cc < 16; cc++) {
            float v = ys[IDX(row, seg*16 + cc)];
            s += v; q += v*v;
        }
        part_s[tx] = s; part_q[tx] = q;
    }
    __syncthreads();
    if (tx < 64) {
        float S = part_s[tx*4] + part_s[tx*4+1] + part_s[tx*4+2] + part_s[tx*4+3];
        float Q = part_q[tx*4] + part_q[tx*4+1] + part_q[tx*4+2] + part_q[tx*4+3];
        float m = S * (1.0f/64.f);
        float var = Q * (1.0f/64.f) - m*m;
        mu[tx] = m; rs[tx] = rsqrtf(var + EPS);
    }
    __syncthreads();
#pragma unroll 4
    for (int i = tx; i < 4096; i += 256) {
        int r = i >> 6, c = i & 63;
        out_base[(size_t)r*64 + c] = (ys[IDX(r,c)] - mu[r]) * rs[r] * g[c] + bb[c];
    }
}

// ---------------- degree / Ahat ----------------
__global__ void deg_kernel(const float* __restrict__ adj) {
    int m = blockIdx.x, tx = threadIdx.x;
    float s = 0.f;
    for (int n = tx; n < Ndim; n += 256) s += adj[m*Ndim + n];
    __shared__ float red[256];
    red[tx] = s; __syncthreads();
#pragma unroll
    for (int st = 128; st > 0; st >>= 1) {
        if (tx < st) red[tx] += red[tx + st];
        __syncthreads();
    }
    if (tx == 0) d_dinv[m] = rsqrtf(fmaxf(red[0] + 1.0f, 1e-12f));
}

__global__ void ahat_kernel(const float* __restrict__ adj) {
    int m = blockIdx.x, n = threadIdx.x;
    float a = adj[m*Ndim + n] + (m == n ? 1.0f : 0.0f);
    d_Ahat[m*Ndim + n] = f2tf32(d_dinv[m] * a * d_dinv[n]);
}

// ---------------- fused QKV (tf32 mma), writes [B,N,T,D] ----------------
__global__ void qkv_gemm(const float* __restrict__ x,
                         const float* __restrict__ Wq, const float* __restrict__ bq,
                         const float* __restrict__ Wk, const float* __restrict__ bk,
                         const float* __restrict__ Wv, const float* __restrict__ bv) {
    __shared__ unsigned As[4096];
    __shared__ unsigned Wt[4096];
    int tx = threadIdx.x;
    int wid = tx >> 5, lane = tx & 31;
    int mrow = (wid >> 1) * 16, ncol = (wid & 1) * 32;
    size_t mbase = (size_t)blockIdx.x * 64;
    int b = (int)(mbase / (Tdim*Ndim));
    int rem = (int)(mbase % (Tdim*Ndim));
    int t = rem / Ndim, nbase = rem % Ndim;
#pragma unroll 4
    for (int i = tx; i < 4096; i += 256) {
        int r = i >> 6, c = i & 63;
        As[IDX(r,c)] = f2tf32(x[(mbase + r)*64 + c]);
    }
    const float* Wm[3] = {Wq, Wk, Wv};
    const float* bm[3] = {bq, bk, bv};
    float* Om[3] = {d_q, d_k, d_v};
#pragma unroll
    for (int m = 0; m < 3; m++) {
        __syncthreads();
        const float* W = Wm[m];
#pragma unroll 4
        for (int i = tx; i < 4096; i += 256) {
            int r = i >> 6, c = i & 63;
            Wt[IDX(r,c)] = f2tf32(W[r*64 + c]);
        }
        __syncthreads();
        float acc[4][4] = {};
        mma_64x64(acc, As, Wt, mrow, ncol, lane);
        float* O = Om[m];
        const float* bias = bm[m];
        int row = mrow + (lane >> 2);
#pragma unroll
        for (int nb = 0; nb < 4; nb++) {
            int col = ncol + nb*8 + 2*(lane & 3);
            float b0v = bias[col], b1v = bias[col+1];
            size_t o0 = ((size_t)(b*Ndim + nbase + row    )*Tdim + t)*64 + col;
            size_t o1 = ((size_t)(b*Ndim + nbase + row + 8)*Tdim + t)*64 + col;
            *(float2*)&O[o0] = make_float2(acc[nb][0] + b0v, acc[nb][1] + b1v);
            *(float2*)&O[o1] = make_float2(acc[nb][2] + b0v, acc[nb][3] + b1v);
        }
    }
}

// ---------------- temporal attention v3: row-softmax in regs, padded smem ----------------
__global__ void attn_kernel() {
    int bn = blockIdx.x;
    int b = bn / Ndim, n = bn % Ndim;
    size_t base = (size_t)bn * Tdim * Ddim;
    __shared__ __align__(16) float qs[Tdim][68];   // padded: stride 68 (17 float4)
    __shared__ float kst[Ddim][25];                // transposed K
    __shared__ __align__(16) float vs[Tdim][Ddim];
    __shared__ float sc[Hdim][Tdim][25];           // padded: conflict-free V-apply
    int tx = threadIdx.x;
    {
        const float4* q4 = (const float4*)(d_q + base);
        const float4* k4 = (const float4*)(d_k + base);
        const float4* v4 = (const float4*)(d_v + base);
        float4* qs4 = (float4*)&qs[0][0];
        float4* vs4 = (float4*)&vs[0][0];
        for (int i = tx; i < Tdim*16; i += 256) {
            int t = i >> 4, f4 = i & 15;
            qs4[t*17 + f4] = q4[i];
            vs4[i] = v4[i];
            float4 kv = k4[i];
            int d = f4 * 4;
            kst[d+0][t] = kv.x; kst[d+1][t] = kv.y; kst[d+2][t] = kv.z; kst[d+3][t] = kv.w;
        }
    }
    __syncthreads();
    // scores + softmax: one (h, tq) row per thread, all in registers
    if (tx < Hdim*Tdim) {
        int h = tx / Tdim, tq = tx % Tdim;
        float qreg[HD];
#pragma unroll
        for (int d = 0; d < HD; d++) qreg[d] = qs[tq][h*HD + d];
        float row[Tdim];
        float m = -1e30f;
#pragma unroll
        for (int tk = 0; tk < Tdim; tk++) {
            float s = 0.f;
#pragma unroll
            for (int d = 0; d < HD; d++) s += qreg[d] * kst[h*HD + d][tk];
            s *= 0.25f;
            row[tk] = s;
            m = fmaxf(m, s);
        }
        float sum = 0.f;
#pragma unroll
        for (int tk = 0; tk < Tdim; tk++) {
            float e = __expf(row[tk] - m);
            row[tk] = e; sum += e;
        }
        float inv = 1.0f / sum;
#pragma unroll
        for (int tk = 0; tk < Tdim; tk++) sc[h][tq][tk] = row[tk] * inv;
    }
    __syncthreads();
    // V-apply: float4 over d; sc reads now conflict-free (pad 25)
    const float4* vs4 = (const float4*)&vs[0][0];
    float4* att4 = (float4*)d_att;
    for (int i = tx; i < Tdim*16; i += 256) {
        int tq = i >> 4, d4 = i & 15;
        int h = d4 >> 2;
        float4 o = make_float4(0.f, 0.f, 0.f, 0.f);
#pragma unroll
        for (int tk = 0; tk < Tdim; tk++) {
            float s = sc[h][tq][tk];
            float4 vv = vs4[tk*16 + d4];
            o.x += s*vv.x; o.y += s*vv.y; o.z += s*vv.z; o.w += s*vv.w;
        }
        att4[(((size_t)b*Tdim + tq)*Ndim + n)*16 + d4] = o;
    }
}

// ---------------- O-proj (tf32 mma) + residual + LN -> d_h ----------------
__global__ void oproj_ln(const float* __restrict__ x,
                         const float* __restrict__ Wo, const float* __restrict__ bo,
                         const float* __restrict__ g, const float* __restrict__ bb) {
    __shared__ unsigned As[4096];
    __shared__ unsigned Wt[4096];
    int tx = threadIdx.x;
    int wid = tx >> 5, lane = tx & 31;
    int mrow = (wid >> 1) * 16, ncol = (wid & 1) * 32;
    size_t mbase = (size_t)blockIdx.x * 64;
#pragma unroll 4
    for (int i = tx; i < 4096; i += 256) {
        int r = i >> 6, c = i & 63;
        As[IDX(r,c)] = f2tf32(d_att[(mbase + r)*64 + c]);
        Wt[IDX(r,c)] = f2tf32(Wo[r*64 + c]);
    }
    __syncthreads();
    float acc[4][4] = {};
    mma_64x64(acc, As, Wt, mrow, ncol, lane);
    __syncthreads();
    float* ys = (float*)As;
    {
        int row = mrow + (lane >> 2);
#pragma unroll
        for (int nb = 0; nb < 4; nb++) {
            int col = ncol + nb*8 + 2*(lane & 3);
            float2 x0 = *(const float2*)&x[(mbase + row    )*64 + col];
            float2 x1 = *(const float2*)&x[(mbase + row + 8)*64 + col];
            ys[IDX(row,   col  )] = acc[nb][0] + bo[col]   + x0.x;
            ys[IDX(row,   col+1)] = acc[nb][1] + bo[col+1] + x0.y;
            ys[IDX(row+8, col  )] = acc[nb][2] + bo[col]   + x1.x;
            ys[IDX(row+8, col+1)] = acc[nb][3] + bo[col+1] + x1.y;
        }
    }
    __syncthreads();
    ln_epilogue(ys, (float*)Wt, g, bb, d_h + mbase*64, tx);
}

// ---------------- graph GEMM: cp.async double-buffered pipeline ----------------
__global__ void graph_gemm_tf32(int stage) {
    const float* __restrict__ Hin = stage ? (const float*)d_p1 : (const float*)d_h;
    float* __restrict__ Hout      = stage ? d_p2 : d_p1;
    __shared__ unsigned As[2][4096];   // Ahat tf32 bits
    __shared__ unsigned Bs[2][4096];   // Hin raw fp32 bits
    int tx = threadIdx.x;
    int wid = tx >> 5, lane = tx & 31;
    int mrow = (wid >> 1) * 16, ncol = (wid & 1) * 32;
    int mbase = blockIdx.x * 64;
    size_t hbase = (size_t)blockIdx.y * Ndim * Ddim;

    unsigned int aAddr[2] = { (unsigned int)__cvta_generic_to_shared(As[0]),
                              (unsigned int)__cvta_generic_to_shared(As[1]) };
    unsigned int bAddr[2] = { (unsigned int)__cvta_generic_to_shared(Bs[0]),
                              (unsigned int)__cvta_generic_to_shared(Bs[1]) };

    // issue tile kt into buffer buf
    auto issue = [&](int kt, int buf) {
#pragma unroll
        for (int j = 0; j < 4; j++) {
            int idx = tx + j*256;               // 0..1023 16B-chunks
            int r = idx >> 4, c4 = (idx & 15) << 2;
            unsigned int soff = (unsigned int)IDX(r, c4) << 2;
            cp16(aAddr[buf] + soff, &d_Ahat[(size_t)(mbase + r)*Ndim + kt*64 + c4]);
            cp16(bAddr[buf] + soff, &Hin[hbase + (size_t)(kt*64 + r)*64 + c4]);
        }
        asm volatile("cp.async.commit_group;");
    };

    float acc[4][4] = {};
    issue(0, 0);
    for (int kt = 0; kt < 8; kt++) {
        if (kt < 7) issue(kt + 1, (kt + 1) & 1);
        if (kt < 7) asm volatile("cp.async.wait_group 1;");
        else        asm volatile("cp.async.wait_group 0;");
        __syncthreads();
        mma_64x64_bcvt(acc, As[kt & 1], Bs[kt & 1], mrow, ncol, lane);
        __syncthreads();   // all warps done with this buffer before overwrite
    }
    int row = mbase + mrow + (lane >> 2);
#pragma unroll
    for (int nb = 0; nb < 4; nb++) {
        int col = ncol + nb*8 + 2*(lane & 3);
        *(float2*)&Hout[hbase + (size_t)row*64 + col]     = make_float2(acc[nb][0], acc[nb][1]);
        *(float2*)&Hout[hbase + (size_t)(row+8)*64 + col] = make_float2(acc[nb][2], acc[nb][3]);
    }
}

// ---------------- gc combine (3x tf32 mma) + residual + LN -> d_h2 ----------------
__global__ void gcomb_ln(const float* __restrict__ gcW, const float* __restrict__ gcb,
                         const float* __restrict__ g, const float* __restrict__ bb) {
    __shared__ unsigned In[4096];   // later ys
    __shared__ unsigned Ws[4096];   // later LN scratch
    int tx = threadIdx.x;
    int wid = tx >> 5, lane = tx & 31;
    int mrow = (wid >> 1) * 16, ncol = (wid & 1) * 32;
    size_t mbase = (size_t)blockIdx.x * 64;
    float acc[4][4] = {};
#pragma unroll
    for (int s = 0; s < 3; s++) {
        const float* Hin = (s == 0) ? (const float*)d_h : (s == 1) ? (const float*)d_p1 : (const float*)d_p2;
        __syncthreads();
#pragma unroll 4
        for (int i = tx; i < 4096; i += 256) {
            int r = i >> 6, c = i & 63;
            In[IDX(r,c)] = f2tf32(Hin[(mbase + r)*64 + c]);
            Ws[IDX(r,c)] = f2tf32(gcW[s*4096 + r*64 + c]);
        }
        __syncthreads();
        mma_64x64(acc, In, Ws, mrow, ncol, lane);
    }
    __syncthreads();
    float* ys = (float*)In;
    {
        int row = mrow + (lane >> 2);
#pragma unroll
        for (int nb = 0; nb < 4; nb++) {
            int col = ncol + nb*8 + 2*(lane & 3);
            float gb0 = gcb[col]   + gcb[64+col]   + gcb[128+col];
            float gb1 = gcb[col+1] + gcb[64+col+1] + gcb[128+col+1];
            float2 h0 = *(const float2*)&d_h[(mbase + row    )*64 + col];
            float2 h1 = *(const float2*)&d_h[(mbase + row + 8)*64 + col];
            ys[IDX(row,   col  )] = acc[nb][0] + gb0 + h0.x;
            ys[IDX(row,   col+1)] = acc[nb][1] + gb1 + h0.y;
            ys[IDX(row+8, col  )] = acc[nb][2] + gb0 + h1.x;
            ys[IDX(row+8, col+1)] = acc[nb][3] + gb1 + h1.y;
        }
    }
    __syncthreads();
    ln_epilogue(ys, (float*)Ws, g, bb, d_h2 + mbase*64, tx);
}

// ---------------- FFN via tf32 mma + residual + LN ----------------
__global__ void ffn_ln(const float* __restrict__ W1, const float* __restrict__ b1,
                       const float* __restrict__ W2, const float* __restrict__ b2,
                       const float* __restrict__ g, const float* __restrict__ bb,
                       float* __restrict__ out) {
    __shared__ float    Asm[4096];
    __shared__ unsigned Wt[4096];
    __shared__ unsigned Gc[4096];
    int tx = threadIdx.x;
    int wid = tx >> 5, lane = tx & 31;
    int mrow = (wid >> 1) * 16, ncol = (wid & 1) * 32;
    size_t mbase = (size_t)blockIdx.x * 64;
#pragma unroll 4
    for (int i = tx; i < 4096; i += 256) {
        int r = i >> 6, c = i & 63;
        Asm[IDX(r,c)] = d_h2[(mbase + r)*64 + c];
    }
    float acc[4][4] = {};
#pragma unroll
    for (int ch = 0; ch < 4; ch++) {
        __syncthreads();
#pragma unroll 4
        for (int i = tx; i < 4096; i += 256) {
            int r = i >> 6, c = i & 63;
            Wt[IDX(r,c)] = f2tf32(W1[r*Fdim + ch*64 + c]);
        }
        __syncthreads();
        float p[4][4] = {};
#pragma unroll
        for (int k8 = 0; k8 < 8; k8++) {
            int kk = k8 * 8;
            int ar = mrow + (lane >> 2), ac = kk + (lane & 3);
            unsigned a0 = f2tf32(Asm[IDX(ar,   ac)]);
            unsigned a1 = f2tf32(Asm[IDX(ar+8, ac)]);
            unsigned a2 = f2tf32(Asm[IDX(ar,   ac+4)]);
            unsigned a3 = f2tf32(Asm[IDX(ar+8, ac+4)]);
#pragma unroll
            for (int nb = 0; nb < 4; nb++) {
                int n0 = ncol + nb*8;
                unsigned b0 = Wt[IDX(kk + (lane & 3),     n0 + (lane >> 2))];
                unsigned b1 = Wt[IDX(kk + (lane & 3) + 4, n0 + (lane >> 2))];
                mma_tf32(p[nb], a0, a1, a2, a3, b0, b1);
            }
        }
        {
            int row = mrow + (lane >> 2);
#pragma unroll
            for (int nb = 0; nb < 4; nb++) {
                int col = ncol + nb*8 + 2*(lane & 3);
                float bv0 = b1[ch*64 + col], bv1 = b1[ch*64 + col + 1];
                float v0 = p[nb][0] + bv0, v1 = p[nb][1] + bv1;
                float v2 = p[nb][2] + bv0, v3 = p[nb][3] + bv1;
                Gc[IDX(row,   col  )] = f2tf32(0.5f*v0*(1.0f + erff(v0*0.7071067811865476f)));
                Gc[IDX(row,   col+1)] = f2tf32(0.5f*v1*(1.0f + erff(v1*0.7071067811865476f)));
                Gc[IDX(row+8, col  )] = f2tf32(0.5f*v2*(1.0f + erff(v2*0.7071067811865476f)));
                Gc[IDX(row+8, col+1)] = f2tf32(0.5f*v3*(1.0f + erff(v3*0.7071067811865476f)));
            }
        }
        __syncthreads();
#pragma unroll 4
        for (int i = tx; i < 4096; i += 256) {
            int r = i >> 6, c = i & 63;
            Wt[IDX(r,c)] = f2tf32(W2[(ch*64 + r)*64 + c]);
        }
        __syncthreads();
        mma_64x64(acc, Gc, Wt, mrow, ncol, lane);
    }
    __syncthreads();
    float* ys = (float*)Wt;
    {
        int row = mrow + (lane >> 2);
#pragma unroll
        for (int nb = 0; nb < 4; nb++) {
            int col = ncol + nb*8 + 2*(lane & 3);
            ys[IDX(row,   col  )] = acc[nb][0] + b2[col]   + Asm[IDX(row,   col)];
            ys[IDX(row,   col+1)] = acc[nb][1] + b2[col+1] + Asm[IDX(row,   col+1)];
            ys[IDX(row+8, col  )] = acc[nb][2] + b2[col]   + Asm[IDX(row+8, col)];
            ys[IDX(row+8, col+1)] = acc[nb][3] + b2[col+1] + Asm[IDX(row+8, col+1)];
        }
    }
    __syncthreads();
    ln_epilogue(ys, (float*)Gc, g, bb, out + mbase*64, tx);
}

// ---------------- launch ----------------
extern "C" void kernel_launch(void* const* d_in, const int* in_sizes, int n_in,
                              void* d_out, int out_size) {
    const float* x   = (const float*)d_in[0];
    const float* adj = (const float*)d_in[1];
    const float* Wq  = (const float*)d_in[2];
    const float* bq  = (const float*)d_in[3];
    const float* Wk  = (const float*)d_in[4];
    const float* bk  = (const float*)d_in[5];
    const float* Wv  = (const float*)d_in[6];
    const float* bv  = (const float*)d_in[7];
    const float* Wo  = (const float*)d_in[8];
    const float* bo  = (const float*)d_in[9];
    const float* gcW = (const float*)d_in[10];
    const float* gcb = (const float*)d_in[11];
    const float* W1  = (const float*)d_in[12];
    const float* b1  = (const float*)d_in[13];
    const float* W2  = (const float*)d_in[14];
    const float* b2  = (const float*)d_in[15];
    const float* g_t = (const float*)d_in[16];
    const float* b_t = (const float*)d_in[17];
    const float* g_g = (const float*)d_in[18];
    const float* b_g = (const float*)d_in[19];
    const float* g_f = (const float*)d_in[20];
    const float* b_f = (const float*)d_in[21];
    float* out = (float*)d_out;

    deg_kernel<<<Ndim, 256>>>(adj);
    ahat_kernel<<<Ndim, Ndim>>>(adj);

    qkv_gemm<<<MTOK/64, 256>>>(x, Wq, bq, Wk, bk, Wv, bv);

    attn_kernel<<<Bdim*Ndim, 256>>>();

    oproj_ln<<<MTOK/64, 256>>>(x, Wo, bo, g_t, b_t);

    {
        dim3 grid(8, Bdim*Tdim);
        graph_gemm_tf32<<<grid, 256>>>(0);
        graph_gemm_tf32<<<grid, 256>>>(1);
    }
    gcomb_ln<<<MTOK/64, 256>>>(gcW, gcb, g_g, b_g);

    ffn_ln<<<MTOK/64, 256>>>(W1, b1, W2, b2, g_f, b_f, out);
}

// round 16
// speedup vs baseline: 2.1876x; 1.2520x over previous
#include <cuda_runtime.h>
#include <cuda_bf16.h>
#include <math.h>
#include <stdint.h>

#define Bdim 16
#define Tdim 24
#define Ndim 512
#define Ddim 64
#define Hdim 4
#define HD   16
#define Fdim 256
#define MTOK (Bdim*Tdim*Ndim)   // 196608
#define EPS  1e-5f

// XOR-quad swizzle for stride-64 fp32/tf32 smem tiles
#define IDX(r,c) (((r)<<6) | (((c)&3) | (((((c)>>2) ^ ((r)&7))&15) << 2)))

// ---------------- scratch (device-only references) ----------------
__device__ float d_q[MTOK*Ddim];
__device__ float d_k[MTOK*Ddim];
__device__ float d_v[MTOK*Ddim];
__device__ float d_att[MTOK*Ddim];
__device__ float d_h[MTOK*Ddim];
__device__ float d_p1[MTOK*Ddim];
__device__ float d_p2[MTOK*Ddim];
__device__ float d_h2[MTOK*Ddim];
__device__ unsigned d_Ahat[Ndim*Ndim];   // tf32 bits, pre-converted
__device__ float d_dinv[Ndim];

__device__ __forceinline__ unsigned f2tf32(float x) {
    unsigned r;
    asm("cvt.rna.tf32.f32 %0, %1;" : "=r"(r) : "f"(x));
    return r;
}

__device__ __forceinline__ void cp16(unsigned int dst, const void* src) {
    asm volatile("cp.async.cg.shared.global [%0], [%1], 16;" :: "r"(dst), "l"(src));
}
#define CP_COMMIT() asm volatile("cp.async.commit_group;")
#define CP_WAIT0()  asm volatile("cp.async.wait_group 0;")

__device__ __forceinline__ void mma_tf32(float c[4], unsigned a0, unsigned a1,
                                         unsigned a2, unsigned a3,
                                         unsigned b0, unsigned b1) {
    asm volatile(
        "mma.sync.aligned.m16n8k8.row.col.f32.tf32.tf32.f32 "
        "{%0,%1,%2,%3}, {%4,%5,%6,%7}, {%8,%9}, {%0,%1,%2,%3};"
        : "+f"(c[0]), "+f"(c[1]), "+f"(c[2]), "+f"(c[3])
        : "r"(a0), "r"(a1), "r"(a2), "r"(a3), "r"(b0), "r"(b1));
}

// 64x64x64 MMA tile: As [m][k], Bs [k][n], both tf32 swizzled. 8 warps.
__device__ __forceinline__ void mma_64x64(float acc[4][4], const unsigned* As,
                                          const unsigned* Bs, int mrow, int ncol, int lane) {
#pragma unroll
    for (int k8 = 0; k8 < 8; k8++) {
        int kk = k8 * 8;
        int ar = mrow + (lane >> 2), ac = kk + (lane & 3);
        unsigned a0 = As[IDX(ar,   ac)];
        unsigned a1 = As[IDX(ar+8, ac)];
        unsigned a2 = As[IDX(ar,   ac+4)];
        unsigned a3 = As[IDX(ar+8, ac+4)];
#pragma unroll
        for (int nb = 0; nb < 4; nb++) {
            int n0 = ncol + nb*8;
            unsigned b0 = Bs[IDX(kk + (lane & 3),     n0 + (lane >> 2))];
            unsigned b1 = Bs[IDX(kk + (lane & 3) + 4, n0 + (lane >> 2))];
            mma_tf32(acc[nb], a0, a1, a2, a3, b0, b1);
        }
    }
}

// Variant: Bs raw fp32 bits, convert at fragment load (As already tf32).
__device__ __forceinline__ void mma_64x64_bcvt(float acc[4][4], const unsigned* As,
                                               const unsigned* Bs, int mrow, int ncol, int lane) {
#pragma unroll
    for (int k8 = 0; k8 < 8; k8++) {
        int kk = k8 * 8;
        int ar = mrow + (lane >> 2), ac = kk + (lane & 3);
        unsigned a0 = As[IDX(ar,   ac)];
        unsigned a1 = As[IDX(ar+8, ac)];
        unsigned a2 = As[IDX(ar,   ac+4)];
        unsigned a3 = As[IDX(ar+8, ac+4)];
#pragma unroll
        for (int nb = 0; nb < 4; nb++) {
            int n0 = ncol + nb*8;
            unsigned b0 = f2tf32(__uint_as_float(Bs[IDX(kk + (lane & 3),     n0 + (lane >> 2))]));
            unsigned b1 = f2tf32(__uint_as_float(Bs[IDX(kk + (lane & 3) + 4, n0 + (lane >> 2))]));
            mma_tf32(acc[nb], a0, a1, a2, a3, b0, b1);
        }
    }
}

// Variant: BOTH operands raw fp32 bits, convert at fragment load.
__device__ __forceinline__ void mma_64x64_abcvt(float acc[4][4], const unsigned* As,
                                                const unsigned* Bs, int mrow, int ncol, int lane) {
#pragma unroll
    for (int k8 = 0; k8 < 8; k8++) {
        int kk = k8 * 8;
        int ar = mrow + (lane >> 2), ac = kk + (lane & 3);
        unsigned a0 = f2tf32(__uint_as_float(As[IDX(ar,   ac)]));
        unsigned a1 = f2tf32(__uint_as_float(As[IDX(ar+8, ac)]));
        unsigned a2 = f2tf32(__uint_as_float(As[IDX(ar,   ac+4)]));
        unsigned a3 = f2tf32(__uint_as_float(As[IDX(ar+8, ac+4)]));
#pragma unroll
        for (int nb = 0; nb < 4; nb++) {
            int n0 = ncol + nb*8;
            unsigned b0 = f2tf32(__uint_as_float(Bs[IDX(kk + (lane & 3),     n0 + (lane >> 2))]));
            unsigned b1 = f2tf32(__uint_as_float(Bs[IDX(kk + (lane & 3) + 4, n0 + (lane >> 2))]));
            mma_tf32(acc[nb], a0, a1, a2, a3, b0, b1);
        }
    }
}

// shared LN helper: ys is swizzled fp32 [64][64]; scratch >= 640 floats
__device__ __forceinline__ void ln_epilogue(const float* ys, float* scratch,
                                            const float* g, const float* bb,
                                            float* out_base, int tx) {
    float* part_s = scratch;
    float* part_q = scratch + 256;
    float* mu     = scratch + 512;
    float* rs     = scratch + 576;
    {
        int row = tx >> 2, seg = tx & 3;
        float s = 0.f, q = 0.f;
#pragma unroll
        for (int cc = 0; cc < 16; cc++) {
            float v = ys[IDX(row, seg*16 + cc)];
            s += v; q += v*v;
        }
        part_s[tx] = s; part_q[tx] = q;
    }
    __syncthreads();
    if (tx < 64) {
        float S = part_s[tx*4] + part_s[tx*4+1] + part_s[tx*4+2] + part_s[tx*4+3];
        float Q = part_q[tx*4] + part_q[tx*4+1] + part_q[tx*4+2] + part_q[tx*4+3];
        float m = S * (1.0f/64.f);
        float var = Q * (1.0f/64.f) - m*m;
        mu[tx] = m; rs[tx] = rsqrtf(var + EPS);
    }
    __syncthreads();
#pragma unroll 4
    for (int i = tx; i < 4096; i += 256) {
        int r = i >> 6, c = i & 63;
        out_base[(size_t)r*64 + c] = (ys[IDX(r,c)] - mu[r]) * rs[r] * g[c] + bb[c];
    }
}

// tile streamer: 64x64 fp32 tile (row stride row_stride floats) -> swizzled smem
__device__ __forceinline__ void issue_tile(unsigned int sAddr, const float* src,
                                           int row_stride, int tx) {
#pragma unroll
    for (int j = 0; j < 4; j++) {
        int idx = tx + j*256;
        int r = idx >> 4, c4 = (idx & 15) << 2;
        cp16(sAddr + ((unsigned int)IDX(r, c4) << 2), src + (size_t)r*row_stride + c4);
    }
}

// ---------------- degree / Ahat ----------------
__global__ void deg_kernel(const float* __restrict__ adj) {
    int m = blockIdx.x, tx = threadIdx.x;
    float s = 0.f;
    for (int n = tx; n < Ndim; n += 256) s += adj[m*Ndim + n];
    __shared__ float red[256];
    red[tx] = s; __syncthreads();
#pragma unroll
    for (int st = 128; st > 0; st >>= 1) {
        if (tx < st) red[tx] += red[tx + st];
        __syncthreads();
    }
    if (tx == 0) d_dinv[m] = rsqrtf(fmaxf(red[0] + 1.0f, 1e-12f));
}

__global__ void ahat_kernel(const float* __restrict__ adj) {
    int m = blockIdx.x, n = threadIdx.x;
    float a = adj[m*Ndim + n] + (m == n ? 1.0f : 0.0f);
    d_Ahat[m*Ndim + n] = f2tf32(d_dinv[m] * a * d_dinv[n]);
}

// ---------------- fused QKV (tf32 mma, weight prefetch), writes [B,N,T,D] ----------------
__global__ void qkv_gemm(const float* __restrict__ x,
                         const float* __restrict__ Wq, const float* __restrict__ bq,
                         const float* __restrict__ Wk, const float* __restrict__ bk,
                         const float* __restrict__ Wv, const float* __restrict__ bv) {
    __shared__ unsigned As[4096];
    __shared__ unsigned Wt[2][4096];   // raw fp32 weight tiles
    int tx = threadIdx.x;
    int wid = tx >> 5, lane = tx & 31;
    int mrow = (wid >> 1) * 16, ncol = (wid & 1) * 32;
    size_t mbase = (size_t)blockIdx.x * 64;
    int b = (int)(mbase / (Tdim*Ndim));
    int rem = (int)(mbase % (Tdim*Ndim));
    int t = rem / Ndim, nbase = rem % Ndim;
    unsigned int wAddr[2] = { (unsigned int)__cvta_generic_to_shared(Wt[0]),
                              (unsigned int)__cvta_generic_to_shared(Wt[1]) };
    const float* Wm[3] = {Wq, Wk, Wv};
    const float* bm[3] = {bq, bk, bv};
    float* Om[3] = {d_q, d_k, d_v};

    issue_tile(wAddr[0], Wm[0], 64, tx); CP_COMMIT();
#pragma unroll 4
    for (int i = tx; i < 4096; i += 256) {
        int r = i >> 6, c = i & 63;
        As[IDX(r,c)] = f2tf32(x[(mbase + r)*64 + c]);
    }
#pragma unroll
    for (int m = 0; m < 3; m++) {
        CP_WAIT0();
        __syncthreads();   // W(m) ready; As ready; all warps done with Wt[(m-1)&1]
        if (m < 2) { issue_tile(wAddr[(m+1)&1], Wm[m+1], 64, tx); CP_COMMIT(); }
        float acc[4][4] = {};
        mma_64x64_bcvt(acc, As, Wt[m&1], mrow, ncol, lane);
        float* O = Om[m];
        const float* bias = bm[m];
        int row = mrow + (lane >> 2);
#pragma unroll
        for (int nb = 0; nb < 4; nb++) {
            int col = ncol + nb*8 + 2*(lane & 3);
            float b0v = bias[col], b1v = bias[col+1];
            size_t o0 = ((size_t)(b*Ndim + nbase + row    )*Tdim + t)*64 + col;
            size_t o1 = ((size_t)(b*Ndim + nbase + row + 8)*Tdim + t)*64 + col;
            *(float2*)&O[o0] = make_float2(acc[nb][0] + b0v, acc[nb][1] + b1v);
            *(float2*)&O[o1] = make_float2(acc[nb][2] + b0v, acc[nb][3] + b1v);
        }
    }
}

// ---------------- temporal attention v3 (unchanged from R15) ----------------
__global__ void attn_kernel() {
    int bn = blockIdx.x;
    int b = bn / Ndim, n = bn % Ndim;
    size_t base = (size_t)bn * Tdim * Ddim;
    __shared__ __align__(16) float qs[Tdim][68];
    __shared__ float kst[Ddim][25];
    __shared__ __align__(16) float vs[Tdim][Ddim];
    __shared__ float sc[Hdim][Tdim][25];
    int tx = threadIdx.x;
    {
        const float4* q4 = (const float4*)(d_q + base);
        const float4* k4 = (const float4*)(d_k + base);
        const float4* v4 = (const float4*)(d_v + base);
        float4* qs4 = (float4*)&qs[0][0];
        float4* vs4 = (float4*)&vs[0][0];
        for (int i = tx; i < Tdim*16; i += 256) {
            int t = i >> 4, f4 = i & 15;
            qs4[t*17 + f4] = q4[i];
            vs4[i] = v4[i];
            float4 kv = k4[i];
            int d = f4 * 4;
            kst[d+0][t] = kv.x; kst[d+1][t] = kv.y; kst[d+2][t] = kv.z; kst[d+3][t] = kv.w;
        }
    }
    __syncthreads();
    if (tx < Hdim*Tdim) {
        int h = tx / Tdim, tq = tx % Tdim;
        float qreg[HD];
#pragma unroll
        for (int d = 0; d < HD; d++) qreg[d] = qs[tq][h*HD + d];
        float row[Tdim];
        float m = -1e30f;
#pragma unroll
        for (int tk = 0; tk < Tdim; tk++) {
            float s = 0.f;
#pragma unroll
            for (int d = 0; d < HD; d++) s += qreg[d] * kst[h*HD + d][tk];
            s *= 0.25f;
            row[tk] = s;
            m = fmaxf(m, s);
        }
        float sum = 0.f;
#pragma unroll
        for (int tk = 0; tk < Tdim; tk++) {
            float e = __expf(row[tk] - m);
            row[tk] = e; sum += e;
        }
        float inv = 1.0f / sum;
#pragma unroll
        for (int tk = 0; tk < Tdim; tk++) sc[h][tq][tk] = row[tk] * inv;
    }
    __syncthreads();
    const float4* vs4 = (const float4*)&vs[0][0];
    float4* att4 = (float4*)d_att;
    for (int i = tx; i < Tdim*16; i += 256) {
        int tq = i >> 4, d4 = i & 15;
        int h = d4 >> 2;
        float4 o = make_float4(0.f, 0.f, 0.f, 0.f);
#pragma unroll
        for (int tk = 0; tk < Tdim; tk++) {
            float s = sc[h][tq][tk];
            float4 vv = vs4[tk*16 + d4];
            o.x += s*vv.x; o.y += s*vv.y; o.z += s*vv.z; o.w += s*vv.w;
        }
        att4[(((size_t)b*Tdim + tq)*Ndim + n)*16 + d4] = o;
    }
}

// ---------------- O-proj (cp.async loads) + residual + LN -> d_h ----------------
__global__ void oproj_ln(const float* __restrict__ x,
                         const float* __restrict__ Wo, const float* __restrict__ bo,
                         const float* __restrict__ g, const float* __restrict__ bb) {
    __shared__ unsigned As[4096];   // raw att fp32; later ys
    __shared__ unsigned Wt[4096];   // raw Wo fp32; later LN scratch
    int tx = threadIdx.x;
    int wid = tx >> 5, lane = tx & 31;
    int mrow = (wid >> 1) * 16, ncol = (wid & 1) * 32;
    size_t mbase = (size_t)blockIdx.x * 64;
    unsigned int aAddr = (unsigned int)__cvta_generic_to_shared(As);
    unsigned int wAddr = (unsigned int)__cvta_generic_to_shared(Wt);
    issue_tile(aAddr, d_att + mbase*64, 64, tx);
    issue_tile(wAddr, Wo, 64, tx);
    CP_COMMIT();
    CP_WAIT0();
    __syncthreads();
    float acc[4][4] = {};
    mma_64x64_abcvt(acc, As, Wt, mrow, ncol, lane);
    __syncthreads();
    float* ys = (float*)As;
    {
        int row = mrow + (lane >> 2);
#pragma unroll
        for (int nb = 0; nb < 4; nb++) {
            int col = ncol + nb*8 + 2*(lane & 3);
            float2 x0 = *(const float2*)&x[(mbase + row    )*64 + col];
            float2 x1 = *(const float2*)&x[(mbase + row + 8)*64 + col];
            ys[IDX(row,   col  )] = acc[nb][0] + bo[col]   + x0.x;
            ys[IDX(row,   col+1)] = acc[nb][1] + bo[col+1] + x0.y;
            ys[IDX(row+8, col  )] = acc[nb][2] + bo[col]   + x1.x;
            ys[IDX(row+8, col+1)] = acc[nb][3] + bo[col+1] + x1.y;
        }
    }
    __syncthreads();
    ln_epilogue(ys, (float*)Wt, g, bb, d_h + mbase*64, tx);
}

// ---------------- graph GEMM: cp.async double-buffered pipeline (R15) ----------------
__global__ void graph_gemm_tf32(int stage) {
    const float* __restrict__ Hin = stage ? (const float*)d_p1 : (const float*)d_h;
    float* __restrict__ Hout      = stage ? d_p2 : d_p1;
    __shared__ unsigned As[2][4096];   // Ahat tf32 bits
    __shared__ unsigned Bs[2][4096];   // Hin raw fp32 bits
    int tx = threadIdx.x;
    int wid = tx >> 5, lane = tx & 31;
    int mrow = (wid >> 1) * 16, ncol = (wid & 1) * 32;
    int mbase = blockIdx.x * 64;
    size_t hbase = (size_t)blockIdx.y * Ndim * Ddim;

    unsigned int aAddr[2] = { (unsigned int)__cvta_generic_to_shared(As[0]),
                              (unsigned int)__cvta_generic_to_shared(As[1]) };
    unsigned int bAddr[2] = { (unsigned int)__cvta_generic_to_shared(Bs[0]),
                              (unsigned int)__cvta_generic_to_shared(Bs[1]) };

    auto issue = [&](int kt, int buf) {
#pragma unroll
        for (int j = 0; j < 4; j++) {
            int idx = tx + j*256;
            int r = idx >> 4, c4 = (idx & 15) << 2;
            unsigned int soff = (unsigned int)IDX(r, c4) << 2;
            cp16(aAddr[buf] + soff, &d_Ahat[(size_t)(mbase + r)*Ndim + kt*64 + c4]);
            cp16(bAddr[buf] + soff, &Hin[hbase + (size_t)(kt*64 + r)*64 + c4]);
        }
        CP_COMMIT();
    };

    float acc[4][4] = {};
    issue(0, 0);
    for (int kt = 0; kt < 8; kt++) {
        if (kt < 7) issue(kt + 1, (kt + 1) & 1);
        if (kt < 7) asm volatile("cp.async.wait_group 1;");
        else        asm volatile("cp.async.wait_group 0;");
        __syncthreads();
        mma_64x64_bcvt(acc, As[kt & 1], Bs[kt & 1], mrow, ncol, lane);
        __syncthreads();
    }
    int row = mbase + mrow + (lane >> 2);
#pragma unroll
    for (int nb = 0; nb < 4; nb++) {
        int col = ncol + nb*8 + 2*(lane & 3);
        *(float2*)&Hout[hbase + (size_t)row*64 + col]     = make_float2(acc[nb][0], acc[nb][1]);
        *(float2*)&Hout[hbase + (size_t)(row+8)*64 + col] = make_float2(acc[nb][2], acc[nb][3]);
    }
}

// ---------------- gc combine (3x tf32 mma, cp.async prefetch) + residual + LN ----------------
__global__ void gcomb_ln(const float* __restrict__ gcW, const float* __restrict__ gcb,
                         const float* __restrict__ g, const float* __restrict__ bb) {
    __shared__ unsigned In[2][4096];   // raw fp32; In[0] later ys
    __shared__ unsigned Ws[2][4096];   // raw fp32; later LN scratch
    int tx = threadIdx.x;
    int wid = tx >> 5, lane = tx & 31;
    int mrow = (wid >> 1) * 16, ncol = (wid & 1) * 32;
    size_t mbase = (size_t)blockIdx.x * 64;
    unsigned int iAddr[2] = { (unsigned int)__cvta_generic_to_shared(In[0]),
                              (unsigned int)__cvta_generic_to_shared(In[1]) };
    unsigned int wAddr[2] = { (unsigned int)__cvta_generic_to_shared(Ws[0]),
                              (unsigned int)__cvta_generic_to_shared(Ws[1]) };
    const float* Hsrc[3] = { d_h + mbase*64, d_p1 + mbase*64, d_p2 + mbase*64 };

    auto issue = [&](int s, int buf) {
        issue_tile(iAddr[buf], Hsrc[s], 64, tx);
        issue_tile(wAddr[buf], gcW + s*4096, 64, tx);
        CP_COMMIT();
    };

    float acc[4][4] = {};
    issue(0, 0);
#pragma unroll
    for (int s = 0; s < 3; s++) {
        if (s < 2) { issue(s + 1, (s + 1) & 1); asm volatile("cp.async.wait_group 1;"); }
        else       { CP_WAIT0(); }
        __syncthreads();
        mma_64x64_abcvt(acc, In[s & 1], Ws[s & 1], mrow, ncol, lane);
        __syncthreads();   // all warps done with this buffer before overwrite
    }
    float* ys = (float*)In[0];
    {
        int row = mrow + (lane >> 2);
#pragma unroll
        for (int nb = 0; nb < 4; nb++) {
            int col = ncol + nb*8 + 2*(lane & 3);
            float gb0 = gcb[col]   + gcb[64+col]   + gcb[128+col];
            float gb1 = gcb[col+1] + gcb[64+col+1] + gcb[128+col+1];
            float2 h0 = *(const float2*)&d_h[(mbase + row    )*64 + col];
            float2 h1 = *(const float2*)&d_h[(mbase + row + 8)*64 + col];
            ys[IDX(row,   col  )] = acc[nb][0] + gb0 + h0.x;
            ys[IDX(row,   col+1)] = acc[nb][1] + gb1 + h0.y;
            ys[IDX(row+8, col  )] = acc[nb][2] + gb0 + h1.x;
            ys[IDX(row+8, col+1)] = acc[nb][3] + gb1 + h1.y;
        }
    }
    __syncthreads();
    ln_epilogue(ys, (float*)Ws[0], g, bb, d_h2 + mbase*64, tx);
}

// ---------------- FFN (tf32 mma, double-buffered weight chunks) + residual + LN ----------------
__global__ void ffn_ln(const float* __restrict__ W1, const float* __restrict__ b1,
                       const float* __restrict__ W2, const float* __restrict__ b2,
                       const float* __restrict__ g, const float* __restrict__ bb,
                       float* __restrict__ out) {
    __shared__ float    Asm[4096];
    __shared__ unsigned Wt[2][4096];   // [0] = W1 chunks, [1] = W2 chunks (raw fp32)
    __shared__ unsigned Gc[4096];
    int tx = threadIdx.x;
    int wid = tx >> 5, lane = tx & 31;
    int mrow = (wid >> 1) * 16, ncol = (wid & 1) * 32;
    size_t mbase = (size_t)blockIdx.x * 64;
    unsigned int w1Addr = (unsigned int)__cvta_generic_to_shared(Wt[0]);
    unsigned int w2Addr = (unsigned int)__cvta_generic_to_shared(Wt[1]);

    auto issueW1 = [&](int ch) {
#pragma unroll
        for (int j = 0; j < 4; j++) {
            int idx = tx + j*256;
            int r = idx >> 4, c4 = (idx & 15) << 2;
            cp16(w1Addr + ((unsigned int)IDX(r, c4) << 2), &W1[r*Fdim + ch*64 + c4]);
        }
        CP_COMMIT();
    };
    auto issueW2 = [&](int ch) {
#pragma unroll
        for (int j = 0; j < 4; j++) {
            int idx = tx + j*256;
            int r = idx >> 4, c4 = (idx & 15) << 2;
            cp16(w2Addr + ((unsigned int)IDX(r, c4) << 2), &W2[(ch*64 + r)*64 + c4]);
        }
        CP_COMMIT();
    };

    issueW1(0);
#pragma unroll 4
    for (int i = tx; i < 4096; i += 256) {
        int r = i >> 6, c = i & 63;
        Asm[IDX(r,c)] = d_h2[(mbase + r)*64 + c];
    }
    float acc[4][4] = {};
#pragma unroll
    for (int ch = 0; ch < 4; ch++) {
        CP_WAIT0();
        __syncthreads();   // W1(ch) ready; Asm ready; all warps done with Wt[1] from prev phase2
        issueW2(ch);
        // phase1: P = A @ W1c (b from raw fp32 Wt[0])
        float p[4][4] = {};
#pragma unroll
        for (int k8 = 0; k8 < 8; k8++) {
            int kk = k8 * 8;
            int ar = mrow + (lane >> 2), ac = kk + (lane & 3);
            unsigned a0 = f2tf32(Asm[IDX(ar,   ac)]);
            unsigned a1 = f2tf32(Asm[IDX(ar+8, ac)]);
            unsigned a2 = f2tf32(Asm[IDX(ar,   ac+4)]);
            unsigned a3 = f2tf32(Asm[IDX(ar+8, ac+4)]);
#pragma unroll
            for (int nb = 0; nb < 4; nb++) {
                int n0 = ncol + nb*8;
                unsigned b0 = f2tf32(__uint_as_float(Wt[0][IDX(kk + (lane & 3),     n0 + (lane >> 2))]));
                unsigned b1 = f2tf32(__uint_as_float(Wt[0][IDX(kk + (lane & 3) + 4, n0 + (lane >> 2))]));
                mma_tf32(p[nb], a0, a1, a2, a3, b0, b1);
            }
        }
        {
            int row = mrow + (lane >> 2);
#pragma unroll
            for (int nb = 0; nb < 4; nb++) {
                int col = ncol + nb*8 + 2*(lane & 3);
                float bv0 = b1[ch*64 + col], bv1 = b1[ch*64 + col + 1];
                float v0 = p[nb][0] + bv0, v1 = p[nb][1] + bv1;
                float v2 = p[nb][2] + bv0, v3 = p[nb][3] + bv1;
                Gc[IDX(row,   col  )] = f2tf32(0.5f*v0*(1.0f + erff(v0*0.7071067811865476f)));
                Gc[IDX(row,   col+1)] = f2tf32(0.5f*v1*(1.0f + erff(v1*0.7071067811865476f)));
                Gc[IDX(row+8, col  )] = f2tf32(0.5f*v2*(1.0f + erff(v2*0.7071067811865476f)));
                Gc[IDX(row+8, col+1)] = f2tf32(0.5f*v3*(1.0f + erff(v3*0.7071067811865476f)));
            }
        }
        CP_WAIT0();
        __syncthreads();   // W2 ready; Gc visible; all warps done reading Wt[0]
        if (ch < 3) issueW1(ch + 1);
        // phase2: acc += Gc @ W2c (Gc tf32 bits, Wt[1] raw fp32)
        mma_64x64_bcvt(acc, Gc, Wt[1], mrow, ncol, lane);
    }
    __syncthreads();
    float* ys = (float*)Wt[0];
    {
        int row = mrow + (lane >> 2);
#pragma unroll
        for (int nb = 0; nb < 4; nb++) {
            int col = ncol + nb*8 + 2*(lane & 3);
            ys[IDX(row,   col  )] = acc[nb][0] + b2[col]   + Asm[IDX(row,   col)];
            ys[IDX(row,   col+1)] = acc[nb][1] + b2[col+1] + Asm[IDX(row,   col+1)];
            ys[IDX(row+8, col  )] = acc[nb][2] + b2[col]   + Asm[IDX(row+8, col)];
            ys[IDX(row+8, col+1)] = acc[nb][3] + b2[col+1] + Asm[IDX(row+8, col+1)];
        }
    }
    __syncthreads();
    ln_epilogue(ys, (float*)Gc, g, bb, out + mbase*64, tx);
}

// ---------------- launch ----------------
extern "C" void kernel_launch(void* const* d_in, const int* in_sizes, int n_in,
                              void* d_out, int out_size) {
    const float* x   = (const float*)d_in[0];
    const float* adj = (const float*)d_in[1];
    const float* Wq  = (const float*)d_in[2];
    const float* bq  = (const float*)d_in[3];
    const float* Wk  = (const float*)d_in[4];
    const float* bk  = (const float*)d_in[5];
    const float* Wv  = (const float*)d_in[6];
    const float* bv  = (const float*)d_in[7];
    const float* Wo  = (const float*)d_in[8];
    const float* bo  = (const float*)d_in[9];
    const float* gcW = (const float*)d_in[10];
    const float* gcb = (const float*)d_in[11];
    const float* W1  = (const float*)d_in[12];
    const float* b1  = (const float*)d_in[13];
    const float* W2  = (const float*)d_in[14];
    const float* b2  = (const float*)d_in[15];
    const float* g_t = (const float*)d_in[16];
    const float* b_t = (const float*)d_in[17];
    const float* g_g = (const float*)d_in[18];
    const float* b_g = (const float*)d_in[19];
    const float* g_f = (const float*)d_in[20];
    const float* b_f = (const float*)d_in[21];
    float* out = (float*)d_out;

    deg_kernel<<<Ndim, 256>>>(adj);
    ahat_kernel<<<Ndim, Ndim>>>(adj);

    qkv_gemm<<<MTOK/64, 256>>>(x, Wq, bq, Wk, bk, Wv, bv);

    attn_kernel<<<Bdim*Ndim, 256>>>();

    oproj_ln<<<MTOK/64, 256>>>(x, Wo, bo, g_t, b_t);

    {
        dim3 grid(8, Bdim*Tdim);
        graph_gemm_tf32<<<grid, 256>>>(0);
        graph_gemm_tf32<<<grid, 256>>>(1);
    }
    gcomb_ln<<<MTOK/64, 256>>>(gcW, gcb, g_g, b_g);

    ffn_ln<<<MTOK/64, 256>>>(W1, b1, W2, b2, g_f, b_f, out);
}

// round 17
// speedup vs baseline: 2.4794x; 1.1334x over previous
#include <cuda_runtime.h>
#include <cuda_bf16.h>
#include <math.h>
#include <stdint.h>

#define Bdim 16
#define Tdim 24
#define Ndim 512
#define Ddim 64
#define Hdim 4
#define HD   16
#define Fdim 256
#define MTOK (Bdim*Tdim*Ndim)   // 196608
#define EPS  1e-5f

// XOR-quad swizzle for stride-64 fp32/tf32 smem tiles
#define IDX(r,c) (((r)<<6) | (((c)&3) | (((((c)>>2) ^ ((r)&7))&15) << 2)))
// pair-swizzle for stride-32 bf16x2 tiles (keeps 4-pair/16B chunks contiguous)
#define IDXP(r,p) (((r)<<5) | ((p)&3) | (((((p)>>2) ^ ((r)&7)) & 7) << 2))

// ---------------- scratch (device-only references) ----------------
__device__ float d_q[MTOK*Ddim];
__device__ float d_k[MTOK*Ddim];
__device__ float d_v[MTOK*Ddim];
__device__ float d_att[MTOK*Ddim];
__device__ float d_h[MTOK*Ddim];
__device__ float d_p1[MTOK*Ddim];
__device__ float d_p2[MTOK*Ddim];
__device__ float d_h2[MTOK*Ddim];
__device__ unsigned d_Ahat[Ndim*Ndim/2];   // bf16x2 packed pairs along n
__device__ float d_dinv[Ndim];

__device__ __forceinline__ unsigned f2tf32(float x) {
    unsigned r;
    asm("cvt.rna.tf32.f32 %0, %1;" : "=r"(r) : "f"(x));
    return r;
}
// pack {lo, hi} floats -> bf16x2 (lo in low half)
__device__ __forceinline__ unsigned packbf(float lo, float hi) {
    unsigned r;
    asm("cvt.rn.bf16x2.f32 %0, %1, %2;" : "=r"(r) : "f"(hi), "f"(lo));
    return r;
}

__device__ __forceinline__ void cp16(unsigned int dst, const void* src) {
    asm volatile("cp.async.cg.shared.global [%0], [%1], 16;" :: "r"(dst), "l"(src));
}
#define CP_COMMIT() asm volatile("cp.async.commit_group;")
#define CP_WAIT0()  asm volatile("cp.async.wait_group 0;")

__device__ __forceinline__ void mma_tf32(float c[4], unsigned a0, unsigned a1,
                                         unsigned a2, unsigned a3,
                                         unsigned b0, unsigned b1) {
    asm volatile(
        "mma.sync.aligned.m16n8k8.row.col.f32.tf32.tf32.f32 "
        "{%0,%1,%2,%3}, {%4,%5,%6,%7}, {%8,%9}, {%0,%1,%2,%3};"
        : "+f"(c[0]), "+f"(c[1]), "+f"(c[2]), "+f"(c[3])
        : "r"(a0), "r"(a1), "r"(a2), "r"(a3), "r"(b0), "r"(b1));
}

__device__ __forceinline__ void mma_bf16(float c[4], unsigned a0, unsigned a1,
                                         unsigned a2, unsigned a3,
                                         unsigned b0, unsigned b1) {
    asm volatile(
        "mma.sync.aligned.m16n8k16.row.col.f32.bf16.bf16.f32 "
        "{%0,%1,%2,%3}, {%4,%5,%6,%7}, {%8,%9}, {%0,%1,%2,%3};"
        : "+f"(c[0]), "+f"(c[1]), "+f"(c[2]), "+f"(c[3])
        : "r"(a0), "r"(a1), "r"(a2), "r"(a3), "r"(b0), "r"(b1));
}

// 64x64x64 MMA tile: As [m][k], Bs [k][n], both tf32 swizzled. 8 warps.
__device__ __forceinline__ void mma_64x64(float acc[4][4], const unsigned* As,
                                          const unsigned* Bs, int mrow, int ncol, int lane) {
#pragma unroll
    for (int k8 = 0; k8 < 8; k8++) {
        int kk = k8 * 8;
        int ar = mrow + (lane >> 2), ac = kk + (lane & 3);
        unsigned a0 = As[IDX(ar,   ac)];
        unsigned a1 = As[IDX(ar+8, ac)];
        unsigned a2 = As[IDX(ar,   ac+4)];
        unsigned a3 = As[IDX(ar+8, ac+4)];
#pragma unroll
        for (int nb = 0; nb < 4; nb++) {
            int n0 = ncol + nb*8;
            unsigned b0 = Bs[IDX(kk + (lane & 3),     n0 + (lane >> 2))];
            unsigned b1 = Bs[IDX(kk + (lane & 3) + 4, n0 + (lane >> 2))];
            mma_tf32(acc[nb], a0, a1, a2, a3, b0, b1);
        }
    }
}

// Variant: Bs raw fp32 bits, convert at fragment load (As already tf32).
__device__ __forceinline__ void mma_64x64_bcvt(float acc[4][4], const unsigned* As,
                                               const unsigned* Bs, int mrow, int ncol, int lane) {
#pragma unroll
    for (int k8 = 0; k8 < 8; k8++) {
        int kk = k8 * 8;
        int ar = mrow + (lane >> 2), ac = kk + (lane & 3);
        unsigned a0 = As[IDX(ar,   ac)];
        unsigned a1 = As[IDX(ar+8, ac)];
        unsigned a2 = As[IDX(ar,   ac+4)];
        unsigned a3 = As[IDX(ar+8, ac+4)];
#pragma unroll
        for (int nb = 0; nb < 4; nb++) {
            int n0 = ncol + nb*8;
            unsigned b0 = f2tf32(__uint_as_float(Bs[IDX(kk + (lane & 3),     n0 + (lane >> 2))]));
            unsigned b1 = f2tf32(__uint_as_float(Bs[IDX(kk + (lane & 3) + 4, n0 + (lane >> 2))]));
            mma_tf32(acc[nb], a0, a1, a2, a3, b0, b1);
        }
    }
}

// Variant: BOTH operands raw fp32 bits, convert at fragment load.
__device__ __forceinline__ void mma_64x64_abcvt(float acc[4][4], const unsigned* As,
                                                const unsigned* Bs, int mrow, int ncol, int lane) {
#pragma unroll
    for (int k8 = 0; k8 < 8; k8++) {
        int kk = k8 * 8;
        int ar = mrow + (lane >> 2), ac = kk + (lane & 3);
        unsigned a0 = f2tf32(__uint_as_float(As[IDX(ar,   ac)]));
        unsigned a1 = f2tf32(__uint_as_float(As[IDX(ar+8, ac)]));
        unsigned a2 = f2tf32(__uint_as_float(As[IDX(ar,   ac+4)]));
        unsigned a3 = f2tf32(__uint_as_float(As[IDX(ar+8, ac+4)]));
#pragma unroll
        for (int nb = 0; nb < 4; nb++) {
            int n0 = ncol + nb*8;
            unsigned b0 = f2tf32(__uint_as_float(Bs[IDX(kk + (lane & 3),     n0 + (lane >> 2))]));
            unsigned b1 = f2tf32(__uint_as_float(Bs[IDX(kk + (lane & 3) + 4, n0 + (lane >> 2))]));
            mma_tf32(acc[nb], a0, a1, a2, a3, b0, b1);
        }
    }
}

// bf16 64x64x64 tile: Ap packed bf16x2 pairs (IDXP), Bs raw fp32 (IDX), pack at load.
__device__ __forceinline__ void mma_64x64_bf16(float acc[4][4], const unsigned* Ap,
                                               const unsigned* Bs, int mrow, int ncol, int lane) {
#pragma unroll
    for (int k16 = 0; k16 < 4; k16++) {
        int ar = mrow + (lane >> 2);
        int kp = k16*8 + (lane & 3);
        unsigned a0 = Ap[IDXP(ar,   kp)];
        unsigned a1 = Ap[IDXP(ar+8, kp)];
        unsigned a2 = Ap[IDXP(ar,   kp+4)];
        unsigned a3 = Ap[IDXP(ar+8, kp+4)];
        int kr = k16*16 + (lane & 3)*2;
#pragma unroll
        for (int nb = 0; nb < 4; nb++) {
            int n = ncol + nb*8 + (lane >> 2);
            unsigned b0 = packbf(__uint_as_float(Bs[IDX(kr,   n)]),
                                 __uint_as_float(Bs[IDX(kr+1, n)]));
            unsigned b1 = packbf(__uint_as_float(Bs[IDX(kr+8, n)]),
                                 __uint_as_float(Bs[IDX(kr+9, n)]));
            mma_bf16(acc[nb], a0, a1, a2, a3, b0, b1);
        }
    }
}

// shared LN helper: ys is swizzled fp32 [64][64]; scratch >= 640 floats
__device__ __forceinline__ void ln_epilogue(const float* ys, float* scratch,
                                            const float* g, const float* bb,
                                            float* out_base, int tx) {
    float* part_s = scratch;
    float* part_q = scratch + 256;
    float* mu     = scratch + 512;
    float* rs     = scratch + 576;
    {
        int row = tx >> 2, seg = tx & 3;
        float s = 0.f, q = 0.f;
#pragma unroll
        for (int cc = 0; cc < 16; cc++) {
            float v = ys[IDX(row, seg*16 + cc)];
            s += v; q += v*v;
        }
        part_s[tx] = s; part_q[tx] = q;
    }
    __syncthreads();
    if (tx < 64) {
        float S = part_s[tx*4] + part_s[tx*4+1] + part_s[tx*4+2] + part_s[tx*4+3];
        float Q = part_q[tx*4] + part_q[tx*4+1] + part_q[tx*4+2] + part_q[tx*4+3];
        float m = S * (1.0f/64.f);
        float var = Q * (1.0f/64.f) - m*m;
        mu[tx] = m; rs[tx] = rsqrtf(var + EPS);
    }
    __syncthreads();
#pragma unroll 4
    for (int i = tx; i < 4096; i += 256) {
        int r = i >> 6, c = i & 63;
        out_base[(size_t)r*64 + c] = (ys[IDX(r,c)] - mu[r]) * rs[r] * g[c] + bb[c];
    }
}

// tile streamer: 64x64 fp32 tile (row stride row_stride floats) -> swizzled smem
__device__ __forceinline__ void issue_tile(unsigned int sAddr, const float* src,
                                           int row_stride, int tx) {
#pragma unroll
    for (int j = 0; j < 4; j++) {
        int idx = tx + j*256;
        int r = idx >> 4, c4 = (idx & 15) << 2;
        cp16(sAddr + ((unsigned int)IDX(r, c4) << 2), src + (size_t)r*row_stride + c4);
    }
}

// ---------------- degree / Ahat ----------------
__global__ void deg_kernel(const float* __restrict__ adj) {
    int m = blockIdx.x, tx = threadIdx.x;
    float s = 0.f;
    for (int n = tx; n < Ndim; n += 256) s += adj[m*Ndim + n];
    __shared__ float red[256];
    red[tx] = s; __syncthreads();
#pragma unroll
    for (int st = 128; st > 0; st >>= 1) {
        if (tx < st) red[tx] += red[tx + st];
        __syncthreads();
    }
    if (tx == 0) d_dinv[m] = rsqrtf(fmaxf(red[0] + 1.0f, 1e-12f));
}

// pack Ahat as bf16x2 pairs: 256 threads, one pair each
__global__ void ahat_kernel(const float* __restrict__ adj) {
    int m = blockIdx.x, p = threadIdx.x;   // pair index
    int n0 = 2*p, n1 = 2*p + 1;
    float a0 = adj[m*Ndim + n0] + (m == n0 ? 1.0f : 0.0f);
    float a1 = adj[m*Ndim + n1] + (m == n1 ? 1.0f : 0.0f);
    float dm = d_dinv[m];
    d_Ahat[m*(Ndim/2) + p] = packbf(dm * a0 * d_dinv[n0], dm * a1 * d_dinv[n1]);
}

// ---------------- fused QKV (tf32 mma, weight prefetch), writes [B,N,T,D] ----------------
__global__ void qkv_gemm(const float* __restrict__ x,
                         const float* __restrict__ Wq, const float* __restrict__ bq,
                         const float* __restrict__ Wk, const float* __restrict__ bk,
                         const float* __restrict__ Wv, const float* __restrict__ bv) {
    __shared__ unsigned As[4096];
    __shared__ unsigned Wt[2][4096];   // raw fp32 weight tiles
    int tx = threadIdx.x;
    int wid = tx >> 5, lane = tx & 31;
    int mrow = (wid >> 1) * 16, ncol = (wid & 1) * 32;
    size_t mbase = (size_t)blockIdx.x * 64;
    int b = (int)(mbase / (Tdim*Ndim));
    int rem = (int)(mbase % (Tdim*Ndim));
    int t = rem / Ndim, nbase = rem % Ndim;
    unsigned int wAddr[2] = { (unsigned int)__cvta_generic_to_shared(Wt[0]),
                              (unsigned int)__cvta_generic_to_shared(Wt[1]) };
    const float* Wm[3] = {Wq, Wk, Wv};
    const float* bm[3] = {bq, bk, bv};
    float* Om[3] = {d_q, d_k, d_v};

    issue_tile(wAddr[0], Wm[0], 64, tx); CP_COMMIT();
#pragma unroll 4
    for (int i = tx; i < 4096; i += 256) {
        int r = i >> 6, c = i & 63;
        As[IDX(r,c)] = f2tf32(x[(mbase + r)*64 + c]);
    }
#pragma unroll
    for (int m = 0; m < 3; m++) {
        CP_WAIT0();
        __syncthreads();
        if (m < 2) { issue_tile(wAddr[(m+1)&1], Wm[m+1], 64, tx); CP_COMMIT(); }
        float acc[4][4] = {};
        mma_64x64_bcvt(acc, As, Wt[m&1], mrow, ncol, lane);
        float* O = Om[m];
        const float* bias = bm[m];
        int row = mrow + (lane >> 2);
#pragma unroll
        for (int nb = 0; nb < 4; nb++) {
            int col = ncol + nb*8 + 2*(lane & 3);
            float b0v = bias[col], b1v = bias[col+1];
            size_t o0 = ((size_t)(b*Ndim + nbase + row    )*Tdim + t)*64 + col;
            size_t o1 = ((size_t)(b*Ndim + nbase + row + 8)*Tdim + t)*64 + col;
            *(float2*)&O[o0] = make_float2(acc[nb][0] + b0v, acc[nb][1] + b1v);
            *(float2*)&O[o1] = make_float2(acc[nb][2] + b0v, acc[nb][3] + b1v);
        }
    }
}

// ---------------- temporal attention v3 (unchanged) ----------------
__global__ void attn_kernel() {
    int bn = blockIdx.x;
    int b = bn / Ndim, n = bn % Ndim;
    size_t base = (size_t)bn * Tdim * Ddim;
    __shared__ __align__(16) float qs[Tdim][68];
    __shared__ float kst[Ddim][25];
    __shared__ __align__(16) float vs[Tdim][Ddim];
    __shared__ float sc[Hdim][Tdim][25];
    int tx = threadIdx.x;
    {
        const float4* q4 = (const float4*)(d_q + base);
        const float4* k4 = (const float4*)(d_k + base);
        const float4* v4 = (const float4*)(d_v + base);
        float4* qs4 = (float4*)&qs[0][0];
        float4* vs4 = (float4*)&vs[0][0];
        for (int i = tx; i < Tdim*16; i += 256) {
            int t = i >> 4, f4 = i & 15;
            qs4[t*17 + f4] = q4[i];
            vs4[i] = v4[i];
            float4 kv = k4[i];
            int d = f4 * 4;
            kst[d+0][t] = kv.x; kst[d+1][t] = kv.y; kst[d+2][t] = kv.z; kst[d+3][t] = kv.w;
        }
    }
    __syncthreads();
    if (tx < Hdim*Tdim) {
        int h = tx / Tdim, tq = tx % Tdim;
        float qreg[HD];
#pragma unroll
        for (int d = 0; d < HD; d++) qreg[d] = qs[tq][h*HD + d];
        float row[Tdim];
        float m = -1e30f;
#pragma unroll
        for (int tk = 0; tk < Tdim; tk++) {
            float s = 0.f;
#pragma unroll
            for (int d = 0; d < HD; d++) s += qreg[d] * kst[h*HD + d][tk];
            s *= 0.25f;
            row[tk] = s;
            m = fmaxf(m, s);
        }
        float sum = 0.f;
#pragma unroll
        for (int tk = 0; tk < Tdim; tk++) {
            float e = __expf(row[tk] - m);
            row[tk] = e; sum += e;
        }
        float inv = 1.0f / sum;
#pragma unroll
        for (int tk = 0; tk < Tdim; tk++) sc[h][tq][tk] = row[tk] * inv;
    }
    __syncthreads();
    const float4* vs4 = (const float4*)&vs[0][0];
    float4* att4 = (float4*)d_att;
    for (int i = tx; i < Tdim*16; i += 256) {
        int tq = i >> 4, d4 = i & 15;
        int h = d4 >> 2;
        float4 o = make_float4(0.f, 0.f, 0.f, 0.f);
#pragma unroll
        for (int tk = 0; tk < Tdim; tk++) {
            float s = sc[h][tq][tk];
            float4 vv = vs4[tk*16 + d4];
            o.x += s*vv.x; o.y += s*vv.y; o.z += s*vv.z; o.w += s*vv.w;
        }
        att4[(((size_t)b*Tdim + tq)*Ndim + n)*16 + d4] = o;
    }
}

// ---------------- O-proj (cp.async loads) + residual + LN -> d_h ----------------
__global__ void oproj_ln(const float* __restrict__ x,
                         const float* __restrict__ Wo, const float* __restrict__ bo,
                         const float* __restrict__ g, const float* __restrict__ bb) {
    __shared__ unsigned As[4096];
    __shared__ unsigned Wt[4096];
    int tx = threadIdx.x;
    int wid = tx >> 5, lane = tx & 31;
    int mrow = (wid >> 1) * 16, ncol = (wid & 1) * 32;
    size_t mbase = (size_t)blockIdx.x * 64;
    unsigned int aAddr = (unsigned int)__cvta_generic_to_shared(As);
    unsigned int wAddr = (unsigned int)__cvta_generic_to_shared(Wt);
    issue_tile(aAddr, d_att + mbase*64, 64, tx);
    issue_tile(wAddr, Wo, 64, tx);
    CP_COMMIT();
    CP_WAIT0();
    __syncthreads();
    float acc[4][4] = {};
    mma_64x64_abcvt(acc, As, Wt, mrow, ncol, lane);
    __syncthreads();
    float* ys = (float*)As;
    {
        int row = mrow + (lane >> 2);
#pragma unroll
        for (int nb = 0; nb < 4; nb++) {
            int col = ncol + nb*8 + 2*(lane & 3);
            float2 x0 = *(const float2*)&x[(mbase + row    )*64 + col];
            float2 x1 = *(const float2*)&x[(mbase + row + 8)*64 + col];
            ys[IDX(row,   col  )] = acc[nb][0] + bo[col]   + x0.x;
            ys[IDX(row,   col+1)] = acc[nb][1] + bo[col+1] + x0.y;
            ys[IDX(row+8, col  )] = acc[nb][2] + bo[col]   + x1.x;
            ys[IDX(row+8, col+1)] = acc[nb][3] + bo[col+1] + x1.y;
        }
    }
    __syncthreads();
    ln_epilogue(ys, (float*)Wt, g, bb, d_h + mbase*64, tx);
}

// ---------------- graph GEMM: bf16 mma, cp.async double-buffered ----------------
__global__ void graph_gemm_bf16(int stage) {
    const float* __restrict__ Hin = stage ? (const float*)d_p1 : (const float*)d_h;
    float* __restrict__ Hout      = stage ? d_p2 : d_p1;
    __shared__ unsigned Ap[2][2048];   // Ahat bf16x2 pairs (IDXP)
    __shared__ unsigned Bs[2][4096];   // Hin raw fp32 (IDX)
    int tx = threadIdx.x;
    int wid = tx >> 5, lane = tx & 31;
    int mrow = (wid >> 1) * 16, ncol = (wid & 1) * 32;
    int mbase = blockIdx.x * 64;
    size_t hbase = (size_t)blockIdx.y * Ndim * Ddim;

    unsigned int aAddr[2] = { (unsigned int)__cvta_generic_to_shared(Ap[0]),
                              (unsigned int)__cvta_generic_to_shared(Ap[1]) };
    unsigned int bAddr[2] = { (unsigned int)__cvta_generic_to_shared(Bs[0]),
                              (unsigned int)__cvta_generic_to_shared(Bs[1]) };

    auto issue = [&](int kt, int buf) {
        // Ahat: 64 rows x 32 pairs = 512 16B-chunks (8 per row)
#pragma unroll
        for (int j = 0; j < 2; j++) {
            int idx = tx + j*256;              // 0..511
            int r = idx >> 3, p4 = (idx & 7) << 2;
            cp16(aAddr[buf] + ((unsigned int)IDXP(r, p4) << 2),
                 &d_Ahat[(size_t)(mbase + r)*(Ndim/2) + kt*32 + p4]);
        }
        // Hin: 64x64 fp32 = 1024 chunks
#pragma unroll
        for (int j = 0; j < 4; j++) {
            int idx = tx + j*256;
            int r = idx >> 4, c4 = (idx & 15) << 2;
            cp16(bAddr[buf] + ((unsigned int)IDX(r, c4) << 2),
                 &Hin[hbase + (size_t)(kt*64 + r)*64 + c4]);
        }
        CP_COMMIT();
    };

    float acc[4][4] = {};
    issue(0, 0);
    for (int kt = 0; kt < 8; kt++) {
        if (kt < 7) issue(kt + 1, (kt + 1) & 1);
        if (kt < 7) asm volatile("cp.async.wait_group 1;");
        else        asm volatile("cp.async.wait_group 0;");
        __syncthreads();
        mma_64x64_bf16(acc, Ap[kt & 1], Bs[kt & 1], mrow, ncol, lane);
        __syncthreads();
    }
    int row = mbase + mrow + (lane >> 2);
#pragma unroll
    for (int nb = 0; nb < 4; nb++) {
        int col = ncol + nb*8 + 2*(lane & 3);
        *(float2*)&Hout[hbase + (size_t)row*64 + col]     = make_float2(acc[nb][0], acc[nb][1]);
        *(float2*)&Hout[hbase + (size_t)(row+8)*64 + col] = make_float2(acc[nb][2], acc[nb][3]);
    }
}

// ---------------- gc combine (3x tf32 mma, cp.async prefetch) + residual + LN ----------------
__global__ void gcomb_ln(const float* __restrict__ gcW, const float* __restrict__ gcb,
                         const float* __restrict__ g, const float* __restrict__ bb) {
    __shared__ unsigned In[2][4096];
    __shared__ unsigned Ws[2][4096];
    int tx = threadIdx.x;
    int wid = tx >> 5, lane = tx & 31;
    int mrow = (wid >> 1) * 16, ncol = (wid & 1) * 32;
    size_t mbase = (size_t)blockIdx.x * 64;
    unsigned int iAddr[2] = { (unsigned int)__cvta_generic_to_shared(In[0]),
                              (unsigned int)__cvta_generic_to_shared(In[1]) };
    unsigned int wAddr[2] = { (unsigned int)__cvta_generic_to_shared(Ws[0]),
                              (unsigned int)__cvta_generic_to_shared(Ws[1]) };
    const float* Hsrc[3] = { d_h + mbase*64, d_p1 + mbase*64, d_p2 + mbase*64 };

    auto issue = [&](int s, int buf) {
        issue_tile(iAddr[buf], Hsrc[s], 64, tx);
        issue_tile(wAddr[buf], gcW + s*4096, 64, tx);
        CP_COMMIT();
    };

    float acc[4][4] = {};
    issue(0, 0);
#pragma unroll
    for (int s = 0; s < 3; s++) {
        if (s < 2) { issue(s + 1, (s + 1) & 1); asm volatile("cp.async.wait_group 1;"); }
        else       { CP_WAIT0(); }
        __syncthreads();
        mma_64x64_abcvt(acc, In[s & 1], Ws[s & 1], mrow, ncol, lane);
        __syncthreads();
    }
    float* ys = (float*)In[0];
    {
        int row = mrow + (lane >> 2);
#pragma unroll
        for (int nb = 0; nb < 4; nb++) {
            int col = ncol + nb*8 + 2*(lane & 3);
            float gb0 = gcb[col]   + gcb[64+col]   + gcb[128+col];
            float gb1 = gcb[col+1] + gcb[64+col+1] + gcb[128+col+1];
            float2 h0 = *(const float2*)&d_h[(mbase + row    )*64 + col];
            float2 h1 = *(const float2*)&d_h[(mbase + row + 8)*64 + col];
            ys[IDX(row,   col  )] = acc[nb][0] + gb0 + h0.x;
            ys[IDX(row,   col+1)] = acc[nb][1] + gb1 + h0.y;
            ys[IDX(row+8, col  )] = acc[nb][2] + gb0 + h1.x;
            ys[IDX(row+8, col+1)] = acc[nb][3] + gb1 + h1.y;
        }
    }
    __syncthreads();
    ln_epilogue(ys, (float*)Ws[0], g, bb, d_h2 + mbase*64, tx);
}

// ---------------- FFN (tf32 mma, double-buffered weight chunks) + residual + LN ----------------
__global__ void ffn_ln(const float* __restrict__ W1, const float* __restrict__ b1,
                       const float* __restrict__ W2, const float* __restrict__ b2,
                       const float* __restrict__ g, const float* __restrict__ bb,
                       float* __restrict__ out) {
    __shared__ float    Asm[4096];
    __shared__ unsigned Wt[2][4096];
    __shared__ unsigned Gc[4096];
    int tx = threadIdx.x;
    int wid = tx >> 5, lane = tx & 31;
    int mrow = (wid >> 1) * 16, ncol = (wid & 1) * 32;
    size_t mbase = (size_t)blockIdx.x * 64;
    unsigned int w1Addr = (unsigned int)__cvta_generic_to_shared(Wt[0]);
    unsigned int w2Addr = (unsigned int)__cvta_generic_to_shared(Wt[1]);

    auto issueW1 = [&](int ch) {
#pragma unroll
        for (int j = 0; j < 4; j++) {
            int idx = tx + j*256;
            int r = idx >> 4, c4 = (idx & 15) << 2;
            cp16(w1Addr + ((unsigned int)IDX(r, c4) << 2), &W1[r*Fdim + ch*64 + c4]);
        }
        CP_COMMIT();
    };
    auto issueW2 = [&](int ch) {
#pragma unroll
        for (int j = 0; j < 4; j++) {
            int idx = tx + j*256;
            int r = idx >> 4, c4 = (idx & 15) << 2;
            cp16(w2Addr + ((unsigned int)IDX(r, c4) << 2), &W2[(ch*64 + r)*64 + c4]);
        }
        CP_COMMIT();
    };

    issueW1(0);
#pragma unroll 4
    for (int i = tx; i < 4096; i += 256) {
        int r = i >> 6, c = i & 63;
        Asm[IDX(r,c)] = d_h2[(mbase + r)*64 + c];
    }
    float acc[4][4] = {};
#pragma unroll
    for (int ch = 0; ch < 4; ch++) {
        CP_WAIT0();
        __syncthreads();
        issueW2(ch);
        float p[4][4] = {};
#pragma unroll
        for (int k8 = 0; k8 < 8; k8++) {
            int kk = k8 * 8;
            int ar = mrow + (lane >> 2), ac = kk + (lane & 3);
            unsigned a0 = f2tf32(Asm[IDX(ar,   ac)]);
            unsigned a1 = f2tf32(Asm[IDX(ar+8, ac)]);
            unsigned a2 = f2tf32(Asm[IDX(ar,   ac+4)]);
            unsigned a3 = f2tf32(Asm[IDX(ar+8, ac+4)]);
#pragma unroll
            for (int nb = 0; nb < 4; nb++) {
                int n0 = ncol + nb*8;
                unsigned b0 = f2tf32(__uint_as_float(Wt[0][IDX(kk + (lane & 3),     n0 + (lane >> 2))]));
                unsigned b1 = f2tf32(__uint_as_float(Wt[0][IDX(kk + (lane & 3) + 4, n0 + (lane >> 2))]));
                mma_tf32(p[nb], a0, a1, a2, a3, b0, b1);
            }
        }
        {
            int row = mrow + (lane >> 2);
#pragma unroll
            for (int nb = 0; nb < 4; nb++) {
                int col = ncol + nb*8 + 2*(lane & 3);
                float bv0 = b1[ch*64 + col], bv1 = b1[ch*64 + col + 1];
                float v0 = p[nb][0] + bv0, v1 = p[nb][1] + bv1;
                float v2 = p[nb][2] + bv0, v3 = p[nb][3] + bv1;
                Gc[IDX(row,   col  )] = f2tf32(0.5f*v0*(1.0f + erff(v0*0.7071067811865476f)));
                Gc[IDX(row,   col+1)] = f2tf32(0.5f*v1*(1.0f + erff(v1*0.7071067811865476f)));
                Gc[IDX(row+8, col  )] = f2tf32(0.5f*v2*(1.0f + erff(v2*0.7071067811865476f)));
                Gc[IDX(row+8, col+1)] = f2tf32(0.5f*v3*(1.0f + erff(v3*0.7071067811865476f)));
            }
        }
        CP_WAIT0();
        __syncthreads();
        if (ch < 3) issueW1(ch + 1);
        mma_64x64_bcvt(acc, Gc, Wt[1], mrow, ncol, lane);
    }
    __syncthreads();
    float* ys = (float*)Wt[0];
    {
        int row = mrow + (lane >> 2);
#pragma unroll
        for (int nb = 0; nb < 4; nb++) {
            int col = ncol + nb*8 + 2*(lane & 3);
            ys[IDX(row,   col  )] = acc[nb][0] + b2[col]   + Asm[IDX(row,   col)];
            ys[IDX(row,   col+1)] = acc[nb][1] + b2[col+1] + Asm[IDX(row,   col+1)];
            ys[IDX(row+8, col  )] = acc[nb][2] + b2[col]   + Asm[IDX(row+8, col)];
            ys[IDX(row+8, col+1)] = acc[nb][3] + b2[col+1] + Asm[IDX(row+8, col+1)];
        }
    }
    __syncthreads();
    ln_epilogue(ys, (float*)Gc, g, bb, out + mbase*64, tx);
}

// ---------------- launch ----------------
extern "C" void kernel_launch(void* const* d_in, const int* in_sizes, int n_in,
                              void* d_out, int out_size) {
    const float* x   = (const float*)d_in[0];
    const float* adj = (const float*)d_in[1];
    const float* Wq  = (const float*)d_in[2];
    const float* bq  = (const float*)d_in[3];
    const float* Wk  = (const float*)d_in[4];
    const float* bk  = (const float*)d_in[5];
    const float* Wv  = (const float*)d_in[6];
    const float* bv  = (const float*)d_in[7];
    const float* Wo  = (const float*)d_in[8];
    const float* bo  = (const float*)d_in[9];
    const float* gcW = (const float*)d_in[10];
    const float* gcb = (const float*)d_in[11];
    const float* W1  = (const float*)d_in[12];
    const float* b1  = (const float*)d_in[13];
    const float* W2  = (const float*)d_in[14];
    const float* b2  = (const float*)d_in[15];
    const float* g_t = (const float*)d_in[16];
    const float* b_t = (const float*)d_in[17];
    const float* g_g = (const float*)d_in[18];
    const float* b_g = (const float*)d_in[19];
    const float* g_f = (const float*)d_in[20];
    const float* b_f = (const float*)d_in[21];
    float* out = (float*)d_out;

    deg_kernel<<<Ndim, 256>>>(adj);
    ahat_kernel<<<Ndim, 256>>>(adj);

    qkv_gemm<<<MTOK/64, 256>>>(x, Wq, bq, Wk, bk, Wv, bv);

    attn_kernel<<<Bdim*Ndim, 256>>>();

    oproj_ln<<<MTOK/64, 256>>>(x, Wo, bo, g_t, b_t);

    {
        dim3 grid(8, Bdim*Tdim);
        graph_gemm_bf16<<<grid, 256>>>(0);
        graph_gemm_bf16<<<grid, 256>>>(1);
    }
    gcomb_ln<<<MTOK/64, 256>>>(gcW, gcb, g_g, b_g);

    ffn_ln<<<MTOK/64, 256>>>(W1, b1, W2, b2, g_f, b_f, out);
}